// round 4
// baseline (speedup 1.0000x reference)
#include <cuda_runtime.h>
#include <math.h>

#define B_ROWS 65536
#define BLK    512
#define CUN    256
#define TAPSN  100

// ---------------- device scratch (static: no runtime allocation) ----------------
static __device__ float g_h1 [(size_t)B_ROWS * BLK];   // prelu(x@W1^T+b1)
static __device__ float g_yc [(size_t)B_ROWS * CUN];   // normalized + noise
static __device__ float g_dd [(size_t)B_ROWS * BLK];   // prelu(yc@W3^T+b3)
static __device__ float g_W2f[CUN * BLK];              // BN1 folded into W2
static __device__ float g_b2f[CUN];
static __device__ float g_W4f[BLK * BLK];              // BN2 folded into W4
static __device__ float g_b4f[BLK];
static __device__ float g_stats[4 * BLK];              // sum1, sq1, sum2, sq2
static __device__ float g_part [256 * 2 * BLK];        // per-rowblock partial sums
static __device__ float g_nc  [CUN];                   // filtered noise

// ---------------- FIR noise: nc[i] = sum_t fir[t] * (noise*std)[i+49-t] ----------
__global__ void noise_kernel(const float* __restrict__ noise,
                             const float* __restrict__ fir,
                             float* __restrict__ nc,
                             float* __restrict__ out_tail)
{
    int i = threadIdx.x;  // 256 threads, 1 block
    double snr_lin = pow(10.0, 0.7);                 // SNR_DB=7
    float nstd = (float)sqrt(1.0 / (2.0 * 2.0 * snr_lin));  // rate = 512/256 = 2
    float acc = 0.f;
#pragma unroll 4
    for (int t = 0; t < TAPSN; t++) {
        int idx = i + 49 - t;                        // 'same' offset = (100-1)/2
        if (idx >= 0 && idx < CUN)
            acc += fir[t] * (noise[idx] * nstd);
    }
    nc[i] = acc;
    out_tail[i] = acc;   // second output of the reference
}

// ---------------- deterministic column stats (two-pass, no atomics) -------------
// grid (Ncols/256, 256), 256 threads. Each block: 256 rows x 256 cols.
__global__ void stats_partial(const float* __restrict__ H, float* __restrict__ part, int Ncols)
{
    int c  = blockIdx.x * 256 + threadIdx.x;
    int r0 = blockIdx.y * 256;
    float s = 0.f, q = 0.f;
#pragma unroll 4
    for (int r = 0; r < 256; r++) {
        float v = H[(size_t)(r0 + r) * Ncols + c];
        s += v; q += v * v;
    }
    part[((size_t)blockIdx.y * 2    ) * Ncols + c] = s;
    part[((size_t)blockIdx.y * 2 + 1) * Ncols + c] = q;
}

__global__ void stats_reduce(const float* __restrict__ part,
                             float* __restrict__ sum, float* __restrict__ sq, int Ncols)
{
    int c = blockIdx.x * 256 + threadIdx.x;
    float s = 0.f, q = 0.f;
    for (int p = 0; p < 256; p++) {
        s += part[((size_t)p * 2    ) * Ncols + c];
        q += part[((size_t)p * 2 + 1) * Ncols + c];
    }
    sum[c] = s; sq[c] = q;
}

// ---------------- fold BN (training-mode, biased var) into next GEMM ------------
// Wdst[j,k] = Wsrc[j,k]*g[k]*rs[k];  bdst[j] = bsrc[j] + sum_k Wsrc[j,k]*(bt[k]-mu[k]*g[k]*rs[k])
__global__ void fold_kernel(const float* __restrict__ Wsrc, const float* __restrict__ bsrc,
                            const float* __restrict__ gam,  const float* __restrict__ bt,
                            const float* __restrict__ sum,  const float* __restrict__ sq,
                            float* __restrict__ Wdst, float* __restrict__ bdst, int Kin)
{
    int j = blockIdx.x;
    int tid = threadIdx.x;  // 128
    const float invB = 1.0f / (float)B_ROWS;
    float partial = 0.f;
    for (int k = tid; k < Kin; k += 128) {
        float mu  = sum[k] * invB;
        float var = sq[k] * invB - mu * mu;
        float rs  = rsqrtf(var + 1e-5f);
        float s   = gam[k] * rs;
        float w   = Wsrc[(size_t)j * Kin + k];
        Wdst[(size_t)j * Kin + k] = w * s;
        partial += w * (bt[k] - mu * s);
    }
    __shared__ float sh[128];
    sh[tid] = partial; __syncthreads();
    for (int s = 64; s > 0; s >>= 1) { if (tid < s) sh[tid] += sh[tid + s]; __syncthreads(); }
    if (tid == 0) bdst[j] = bsrc[j] + sh[0];
}

// ---------------- tiled fp32 GEMM: C = act(A @ W^T + bias) ----------------------
// A [M,K] row-major, W [N,K] row-major (both K-contiguous -> coalesced loads).
// EPI: 0 = bias only, 1 = bias + PReLU(alpha), 2 = bias + rownorm + noise add.
template <int MT, int NT, int KT, int EPI>
__global__ void __launch_bounds__(256, 2)
gemm_fused(const float* __restrict__ A, const float* __restrict__ W,
           const float* __restrict__ bias, float* __restrict__ C,
           int M, int N, int K,
           const float* __restrict__ alpha_ptr,
           const float* __restrict__ nc)
{
    constexpr int TM = 8, TN = 8;
    constexpr int TX = NT / TN;             // threads along n
    constexpr int TY = MT / TM;             // threads along m  (TX*TY == 256)
    constexpr int KV = KT / 4;              // float4 segments per row

    __shared__ float As[KT][MT + 4];
    __shared__ float Bs[KT][NT + 4];
    __shared__ float red[NT];               // rownorm(MT<=NT) or unused

    const int tid = threadIdx.x;
    const int tx = tid % TX, ty = tid / TX;
    const int m0 = blockIdx.y * MT;
    const int n0 = blockIdx.x * NT;

    float acc[TM][TN];
#pragma unroll
    for (int i = 0; i < TM; i++)
#pragma unroll
        for (int j = 0; j < TN; j++) acc[i][j] = 0.f;

    constexpr int ALD = MT * KV / 256;      // float4 loads per thread (A)
    constexpr int BLD = NT * KV / 256;      // float4 loads per thread (W)

    for (int k0 = 0; k0 < K; k0 += KT) {
        __syncthreads();
#pragma unroll
        for (int i = 0; i < ALD; i++) {
            int f = tid + i * 256;
            int row = f / KV, seg = f % KV;
            float4 v = *(const float4*)(A + (size_t)(m0 + row) * K + k0 + seg * 4);
            As[seg * 4 + 0][row] = v.x; As[seg * 4 + 1][row] = v.y;
            As[seg * 4 + 2][row] = v.z; As[seg * 4 + 3][row] = v.w;
        }
#pragma unroll
        for (int i = 0; i < BLD; i++) {
            int f = tid + i * 256;
            int row = f / KV, seg = f % KV;
            float4 v = *(const float4*)(W + (size_t)(n0 + row) * K + k0 + seg * 4);
            Bs[seg * 4 + 0][row] = v.x; Bs[seg * 4 + 1][row] = v.y;
            Bs[seg * 4 + 2][row] = v.z; Bs[seg * 4 + 3][row] = v.w;
        }
        __syncthreads();
#pragma unroll
        for (int k = 0; k < KT; k++) {
            float4 a0 = *(const float4*)&As[k][ty * TM];
            float4 a1 = *(const float4*)&As[k][ty * TM + 4];
            float4 b0 = *(const float4*)&Bs[k][tx * TN];
            float4 b1 = *(const float4*)&Bs[k][tx * TN + 4];
            float a[8] = {a0.x, a0.y, a0.z, a0.w, a1.x, a1.y, a1.z, a1.w};
            float b[8] = {b0.x, b0.y, b0.z, b0.w, b1.x, b1.y, b1.z, b1.w};
#pragma unroll
            for (int i = 0; i < TM; i++)
#pragma unroll
                for (int j = 0; j < TN; j++)
                    acc[i][j] += a[i] * b[j];
        }
    }

    // -------- epilogue --------
    float bi[TN];
#pragma unroll
    for (int j = 0; j < TN; j++) bi[j] = bias[n0 + tx * TN + j];
#pragma unroll
    for (int i = 0; i < TM; i++)
#pragma unroll
        for (int j = 0; j < TN; j++) acc[i][j] += bi[j];

    if (EPI == 1) {                         // PReLU
        float alpha = *alpha_ptr;
#pragma unroll
        for (int i = 0; i < TM; i++)
#pragma unroll
            for (int j = 0; j < TN; j++) {
                float v = acc[i][j];
                acc[i][j] = v > 0.f ? v : alpha * v;
            }
    }

    if (EPI == 2) {                         // rownorm (NT == N == 256) + noise
        for (int i = tid; i < MT; i += 256) red[i] = 0.f;
        __syncthreads();
#pragma unroll
        for (int i = 0; i < TM; i++) {
            float s = 0.f;
#pragma unroll
            for (int j = 0; j < TN; j++) s += acc[i][j] * acc[i][j];
            atomicAdd(&red[ty * TM + i], s);
        }
        __syncthreads();
#pragma unroll
        for (int i = 0; i < TM; i++) {
            float scale = 16.0f * rsqrtf(red[ty * TM + i]);   // sqrt(CU)=16
#pragma unroll
            for (int j = 0; j < TN; j++)
                acc[i][j] = acc[i][j] * scale + nc[n0 + tx * TN + j];
        }
    }

#pragma unroll
    for (int i = 0; i < TM; i++) {
        float* crow = C + (size_t)(m0 + ty * TM + i) * N + n0 + tx * TN;
        *(float4*)(crow)     = make_float4(acc[i][0], acc[i][1], acc[i][2], acc[i][3]);
        *(float4*)(crow + 4) = make_float4(acc[i][4], acc[i][5], acc[i][6], acc[i][7]);
    }
}

// --------------------------------------------------------------------------------
extern "C" void kernel_launch(void* const* d_in, const int* in_sizes, int n_in,
                              void* d_out, int out_size)
{
    const float* x    = (const float*)d_in[0];
    const float* nz   = (const float*)d_in[1];
    const float* W1   = (const float*)d_in[2];
    const float* b1   = (const float*)d_in[3];
    const float* a1   = (const float*)d_in[4];
    const float* gm1  = (const float*)d_in[5];
    const float* bt1  = (const float*)d_in[6];
    const float* W2   = (const float*)d_in[7];
    const float* b2   = (const float*)d_in[8];
    const float* W3   = (const float*)d_in[9];
    const float* b3   = (const float*)d_in[10];
    const float* a2   = (const float*)d_in[11];
    const float* gm2  = (const float*)d_in[12];
    const float* bt2  = (const float*)d_in[13];
    const float* W4   = (const float*)d_in[14];
    const float* b4   = (const float*)d_in[15];
    const float* fir  = (const float*)d_in[16];
    float* out = (float*)d_out;

    float *h1, *yc, *dd, *W2f, *b2f, *W4f, *b4f, *st, *part, *nc;
    cudaGetSymbolAddress((void**)&h1,  g_h1);
    cudaGetSymbolAddress((void**)&yc,  g_yc);
    cudaGetSymbolAddress((void**)&dd,  g_dd);
    cudaGetSymbolAddress((void**)&W2f, g_W2f);
    cudaGetSymbolAddress((void**)&b2f, g_b2f);
    cudaGetSymbolAddress((void**)&W4f, g_W4f);
    cudaGetSymbolAddress((void**)&b4f, g_b4f);
    cudaGetSymbolAddress((void**)&st,  g_stats);
    cudaGetSymbolAddress((void**)&part,g_part);
    cudaGetSymbolAddress((void**)&nc,  g_nc);

    // 1) FIR-filtered noise (also writes second output at tail of d_out)
    noise_kernel<<<1, 256>>>(nz, fir, nc, out + (size_t)B_ROWS * BLK);

    // 2) h1 = prelu(x @ W1^T + b1)
    gemm_fused<128, 128, 16, 1><<<dim3(BLK / 128, B_ROWS / 128), 256>>>(
        x, W1, b1, h1, B_ROWS, BLK, BLK, a1, nullptr);

    // 3) BN1 stats (deterministic two-pass) and fold into W2
    stats_partial<<<dim3(BLK / 256, B_ROWS / 256), 256>>>(h1, part, BLK);
    stats_reduce<<<BLK / 256, 256>>>(part, st, st + BLK, BLK);
    fold_kernel<<<CUN, 128>>>(W2, b2, gm1, bt1, st, st + BLK, W2f, b2f, BLK);

    // 4) yc = sqrt(CU)*(h1_bn @ W2^T + b2)/||.|| + noise  (rownorm epilogue, full N in CTA)
    gemm_fused<64, 256, 16, 2><<<dim3(1, B_ROWS / 64), 256>>>(
        h1, W2f, b2f, yc, B_ROWS, CUN, BLK, nullptr, nc);

    // 5) d = prelu(yc @ W3^T + b3)
    gemm_fused<128, 128, 16, 1><<<dim3(BLK / 128, B_ROWS / 128), 256>>>(
        yc, W3, b3, dd, B_ROWS, BLK, CUN, a2, nullptr);

    // 6) BN2 stats and fold into W4
    stats_partial<<<dim3(BLK / 256, B_ROWS / 256), 256>>>(dd, part, BLK);
    stats_reduce<<<BLK / 256, 256>>>(part, st + 2 * BLK, st + 3 * BLK, BLK);
    fold_kernel<<<BLK, 128>>>(W4, b4, gm2, bt2, st + 2 * BLK, st + 3 * BLK, W4f, b4f, BLK);

    // 7) out = d_bn @ W4^T + b4
    gemm_fused<128, 128, 16, 0><<<dim3(BLK / 128, B_ROWS / 128), 256>>>(
        dd, W4f, b4f, out, B_ROWS, BLK, BLK, nullptr, nullptr);

    (void)in_sizes; (void)n_in; (void)out_size;
}

// round 7
// speedup vs baseline: 2.0075x; 2.0075x over previous
#include <cuda_runtime.h>
#include <cuda_bf16.h>
#include <math.h>
#include <stdint.h>

#define B_ROWS 65536
#define BLK    512
#define CUN    256
#define TAPSN  100

#define MT     128
#define NTT    128
#define KTT    32
#define STAGES 4
#define RS     40                    // SMEM row stride in elems (32 + 8 pad -> 80B)
#define AELEMS (MT * RS)             // 5120 elems per array per stage
#define STAGE_BYTES (4 * AELEMS * 2) // Ah, Al, Bh, Bl

// ---------------- device scratch (static: no runtime allocation) ----------------
static __device__ __nv_bfloat16 g_xh [(size_t)B_ROWS * BLK], g_xl [(size_t)B_ROWS * BLK];
static __device__ __nv_bfloat16 g_h1h[(size_t)B_ROWS * BLK], g_h1l[(size_t)B_ROWS * BLK];
static __device__ float         g_y  [(size_t)B_ROWS * CUN];
static __device__ __nv_bfloat16 g_ych[(size_t)B_ROWS * CUN], g_ycl[(size_t)B_ROWS * CUN];
static __device__ __nv_bfloat16 g_ddh[(size_t)B_ROWS * BLK], g_ddl[(size_t)B_ROWS * BLK];
static __device__ __nv_bfloat16 g_W1h[BLK * BLK], g_W1l[BLK * BLK];
static __device__ __nv_bfloat16 g_W2h[CUN * BLK], g_W2l[CUN * BLK];
static __device__ __nv_bfloat16 g_W3h[BLK * CUN], g_W3l[BLK * CUN];
static __device__ __nv_bfloat16 g_W4h[BLK * BLK], g_W4l[BLK * BLK];
static __device__ float g_b2f[CUN], g_b4f[BLK];
static __device__ float g_stats[4 * BLK];
static __device__ float g_part [256 * 2 * BLK];
static __device__ float g_nc  [CUN];

// ---------------- helpers ---------------------------------------------------
__device__ __forceinline__ uint32_t s2u(const void* p) {
    return (uint32_t)__cvta_generic_to_shared(p);
}
__device__ __forceinline__ void cpa16(uint32_t d, const void* s) {
    asm volatile("cp.async.cg.shared.global [%0], [%1], 16;" :: "r"(d), "l"(s));
}
__device__ __forceinline__ void ldm4(uint32_t* f, uint32_t a) {
    asm volatile("ldmatrix.sync.aligned.m8n8.x4.shared.b16 {%0,%1,%2,%3}, [%4];"
                 : "=r"(f[0]), "=r"(f[1]), "=r"(f[2]), "=r"(f[3]) : "r"(a));
}
__device__ __forceinline__ void mma_bf(float* d, const uint32_t* a, const uint32_t* b) {
    asm volatile("mma.sync.aligned.m16n8k16.row.col.f32.bf16.bf16.f32 "
                 "{%0,%1,%2,%3}, {%4,%5,%6,%7}, {%8,%9}, {%0,%1,%2,%3};"
                 : "+f"(d[0]), "+f"(d[1]), "+f"(d[2]), "+f"(d[3])
                 : "r"(a[0]), "r"(a[1]), "r"(a[2]), "r"(a[3]), "r"(b[0]), "r"(b[1]));
}
__device__ __forceinline__ uint32_t pkbf(float a, float b) {
    __nv_bfloat162 h = __floats2bfloat162_rn(a, b);   // .x = a (low), .y = b (high)
    return *(uint32_t*)&h;
}
__device__ __forceinline__ float rsd(float v) {
    return v - __bfloat162float(__float2bfloat16_rn(v));
}

// ---------------- small kernels ----------------------------------------------
__global__ void noise_kernel(const float* __restrict__ noise,
                             const float* __restrict__ fir,
                             float* __restrict__ nc,
                             float* __restrict__ out_tail)
{
    int i = threadIdx.x;
    double snr_lin = pow(10.0, 0.7);
    float nstd = (float)sqrt(1.0 / (2.0 * 2.0 * snr_lin));   // rate = 2
    float acc = 0.f;
#pragma unroll 4
    for (int t = 0; t < TAPSN; t++) {
        int idx = i + 49 - t;
        if (idx >= 0 && idx < CUN) acc += fir[t] * (noise[idx] * nstd);
    }
    nc[i] = acc;
    out_tail[i] = acc;
}

__global__ void split_kernel(const float* __restrict__ W,
                             __nv_bfloat16* __restrict__ hi,
                             __nv_bfloat16* __restrict__ lo, int n)
{
    int i = blockIdx.x * 256 + threadIdx.x;
    if (i < n) {
        float v = W[i];
        __nv_bfloat16 h = __float2bfloat16_rn(v);
        hi[i] = h;
        lo[i] = __float2bfloat16_rn(v - __bfloat162float(h));
    }
}

__global__ void splitx_kernel(const float* __restrict__ X,
                              __nv_bfloat16* __restrict__ Xh,
                              __nv_bfloat16* __restrict__ Xl, int n4)
{
    int i = blockIdx.x * 256 + threadIdx.x;
    if (i >= n4) return;
    float4 v = ((const float4*)X)[i];
    uint2 H = make_uint2(pkbf(v.x - rsd(v.x) * 0.f, v.y), pkbf(v.z, v.w)); // hi of each
    // (pkbf already rounds to bf16; hi = bf16(v))
    H = make_uint2(pkbf(v.x, v.y), pkbf(v.z, v.w));
    uint2 L = make_uint2(pkbf(rsd(v.x), rsd(v.y)), pkbf(rsd(v.z), rsd(v.w)));
    ((uint2*)Xh)[i] = H;
    ((uint2*)Xl)[i] = L;
}

__global__ void stats_partial_bf(const __nv_bfloat16* __restrict__ Hh,
                                 const __nv_bfloat16* __restrict__ Hl,
                                 float* __restrict__ part, int Ncols)
{
    int c  = blockIdx.x * 256 + threadIdx.x;
    int r0 = blockIdx.y * 256;
    float s = 0.f, q = 0.f;
#pragma unroll 4
    for (int r = 0; r < 256; r++) {
        size_t idx = (size_t)(r0 + r) * Ncols + c;
        float v = __bfloat162float(Hh[idx]) + __bfloat162float(Hl[idx]);
        s += v; q += v * v;
    }
    part[((size_t)blockIdx.y * 2    ) * Ncols + c] = s;
    part[((size_t)blockIdx.y * 2 + 1) * Ncols + c] = q;
}

__global__ void stats_reduce2(const float* __restrict__ part,
                              float* __restrict__ sum, float* __restrict__ sq, int Ncols)
{
    int c = blockIdx.x;
    int t = threadIdx.x;
    float s = part[((size_t)t * 2    ) * Ncols + c];
    float q = part[((size_t)t * 2 + 1) * Ncols + c];
#pragma unroll
    for (int o = 16; o > 0; o >>= 1) {
        s += __shfl_down_sync(0xFFFFFFFFu, s, o);
        q += __shfl_down_sync(0xFFFFFFFFu, q, o);
    }
    __shared__ float sh[64];
    int w = t >> 5, l = t & 31;
    if (l == 0) { sh[w] = s; sh[32 + w] = q; }
    __syncthreads();
    if (t == 0) {
        float S = 0.f, Q = 0.f;
        for (int i = 0; i < 8; i++) { S += sh[i]; Q += sh[32 + i]; }
        sum[c] = S; sq[c] = Q;
    }
}

__global__ void fold_kernel(const float* __restrict__ Wsrc, const float* __restrict__ bsrc,
                            const float* __restrict__ gam,  const float* __restrict__ bt,
                            const float* __restrict__ sum,  const float* __restrict__ sq,
                            __nv_bfloat16* __restrict__ Whi, __nv_bfloat16* __restrict__ Wlo,
                            float* __restrict__ bdst, int Kin)
{
    int j = blockIdx.x;
    int tid = threadIdx.x;  // 128
    const float invB = 1.0f / (float)B_ROWS;
    float partial = 0.f;
    for (int k = tid; k < Kin; k += 128) {
        float mu  = sum[k] * invB;
        float var = sq[k] * invB - mu * mu;
        float rs  = rsqrtf(var + 1e-5f);
        float s   = gam[k] * rs;
        float w   = Wsrc[(size_t)j * Kin + k];
        float wf  = w * s;
        __nv_bfloat16 h = __float2bfloat16_rn(wf);
        Whi[(size_t)j * Kin + k] = h;
        Wlo[(size_t)j * Kin + k] = __float2bfloat16_rn(wf - __bfloat162float(h));
        partial += w * (bt[k] - mu * s);
    }
    __shared__ float sh[128];
    sh[tid] = partial; __syncthreads();
    for (int s = 64; s > 0; s >>= 1) { if (tid < s) sh[tid] += sh[tid + s]; __syncthreads(); }
    if (tid == 0) bdst[j] = bsrc[j] + sh[0];
}

// rownorm + noise + bf16 hi/lo split: one warp per row (N = 256)
__global__ void rownorm_kernel(const float* __restrict__ Y, const float* __restrict__ nc,
                               __nv_bfloat16* __restrict__ Yh, __nv_bfloat16* __restrict__ Yl)
{
    int wid = threadIdx.x >> 5, lane = threadIdx.x & 31;
    size_t row = (size_t)blockIdx.x * 8 + wid;
    const float* yr = Y + row * CUN;
    float v[8]; float ss = 0.f;
#pragma unroll
    for (int i = 0; i < 8; i++) { v[i] = yr[lane + i * 32]; ss += v[i] * v[i]; }
#pragma unroll
    for (int o = 16; o > 0; o >>= 1) ss += __shfl_xor_sync(0xFFFFFFFFu, ss, o);
    float sc = 16.0f * rsqrtf(ss);   // sqrt(CU) = 16
#pragma unroll
    for (int i = 0; i < 8; i++) {
        int col = lane + i * 32;
        float u = v[i] * sc + nc[col];
        __nv_bfloat16 h = __float2bfloat16_rn(u);
        Yh[row * CUN + col] = h;
        Yl[row * CUN + col] = __float2bfloat16_rn(u - __bfloat162float(h));
    }
}

// ---------------- multistage warp-MMA GEMM: C = epi(A @ W^T + bias) -------------
// A = (AH + AL) bf16 [M,K]; W = (BH + BL) bf16 [N,K]. 3-term split per k16.
// EPI: 0 -> fp32 out (Cf); 1 -> PReLU then bf16 hi/lo out (Ch, Cl).
template <int EPI>
__global__ void __launch_bounds__(256, 1)
gemm_mma(const __nv_bfloat16* __restrict__ AH, const __nv_bfloat16* __restrict__ AL,
         const __nv_bfloat16* __restrict__ BH, const __nv_bfloat16* __restrict__ BL,
         const float* __restrict__ bias,
         float* __restrict__ Cf, __nv_bfloat16* __restrict__ Ch, __nv_bfloat16* __restrict__ Cl,
         int M, int N, int K, const float* __restrict__ alpha_ptr)
{
    extern __shared__ char smem[];
    float* bias_s = (float*)smem;
    char* stage0 = smem + 1024;
    const int tid = threadIdx.x;
    const int lane = tid & 31, wid = tid >> 5;
    const int wm = wid & 1, wn = wid >> 1;        // 2 x 4 warp grid, warp tile 64x32
    const int m0 = blockIdx.y * MT, n0 = blockIdx.x * NTT;

    if (tid < NTT) bias_s[tid] = bias[n0 + tid];

    float acc[4][4][4];
#pragma unroll
    for (int i = 0; i < 4; i++)
#pragma unroll
        for (int j = 0; j < 4; j++)
#pragma unroll
            for (int r = 0; r < 4; r++) acc[i][j][r] = 0.f;

    const int nit = K / KTT;

    auto load_stage = [&](int s, int k0) {
        uint32_t sb = s2u(stage0 + s * STAGE_BYTES);
#pragma unroll
        for (int i = 0; i < 2; i++) {
            int ch = tid + i * 256;
            int r = ch >> 2, c = ch & 3;
            uint32_t doff = (uint32_t)(r * RS * 2 + c * 16);
            size_t ao = (size_t)(m0 + r) * K + k0 + c * 8;
            size_t bo = (size_t)(n0 + r) * K + k0 + c * 8;
            cpa16(sb                  + doff, AH + ao);
            cpa16(sb +     AELEMS * 2 + doff, AL + ao);
            cpa16(sb + 2 * AELEMS * 2 + doff, BH + bo);
            cpa16(sb + 3 * AELEMS * 2 + doff, BL + bo);
        }
    };

    for (int s = 0; s < STAGES - 1; s++) {
        if (s < nit) load_stage(s, s * KTT);
        asm volatile("cp.async.commit_group;" ::: "memory");
    }

    // per-thread fragment address offsets (stage-relative)
    const uint32_t aoff = (uint32_t)(((wm * 64 + (lane & 15)) * RS + (lane >> 4) * 8) * 2);
    const uint32_t boff = (uint32_t)(((wn * 32 + (lane & 7) + ((lane >> 4) << 3)) * RS
                                      + ((lane >> 3) & 1) * 8) * 2);

    for (int it = 0; it < nit; it++) {
        asm volatile("cp.async.wait_group 2;" ::: "memory");
        __syncthreads();
        int ns = it + STAGES - 1;
        if (ns < nit) load_stage(ns % STAGES, ns * KTT);
        asm volatile("cp.async.commit_group;" ::: "memory");

        uint32_t sb  = s2u(stage0 + (it % STAGES) * STAGE_BYTES);
        uint32_t sAh = sb, sAl = sb + AELEMS * 2;
        uint32_t sBh = sb + 2 * AELEMS * 2, sBl = sb + 3 * AELEMS * 2;
#pragma unroll
        for (int k16 = 0; k16 < 2; k16++) {
            uint32_t ko = k16 * 32;   // 16 bf16 = 32 bytes
            uint32_t ah[4][4], al[4][4], bh[4][2], bl[4][2];
#pragma unroll
            for (int i = 0; i < 4; i++) {
                ldm4(ah[i], sAh + aoff + i * 16 * RS * 2 + ko);
                ldm4(al[i], sAl + aoff + i * 16 * RS * 2 + ko);
            }
#pragma unroll
            for (int p = 0; p < 2; p++) {
                uint32_t t[4];
                ldm4(t, sBh + boff + p * 16 * RS * 2 + ko);
                bh[p*2][0] = t[0]; bh[p*2][1] = t[1]; bh[p*2+1][0] = t[2]; bh[p*2+1][1] = t[3];
                ldm4(t, sBl + boff + p * 16 * RS * 2 + ko);
                bl[p*2][0] = t[0]; bl[p*2][1] = t[1]; bl[p*2+1][0] = t[2]; bl[p*2+1][1] = t[3];
            }
#pragma unroll
            for (int i = 0; i < 4; i++)
#pragma unroll
                for (int j = 0; j < 4; j++) {
                    mma_bf(acc[i][j], ah[i], bh[j]);
                    mma_bf(acc[i][j], ah[i], bl[j]);
                    mma_bf(acc[i][j], al[i], bh[j]);
                }
        }
    }

    // -------- epilogue --------
    float alpha = 0.f;
    if (EPI == 1) alpha = *alpha_ptr;
    const int qr = lane >> 2, qc = (lane & 3) * 2;
#pragma unroll
    for (int i = 0; i < 4; i++) {
        int r0 = m0 + wm * 64 + i * 16 + qr;
#pragma unroll
        for (int j = 0; j < 4; j++) {
            int cj = wn * 32 + j * 8 + qc;
            float b0 = bias_s[cj], b1 = bias_s[cj + 1];
            float v00 = acc[i][j][0] + b0, v01 = acc[i][j][1] + b1;
            float v10 = acc[i][j][2] + b0, v11 = acc[i][j][3] + b1;
            if (EPI == 1) {
                v00 = v00 > 0.f ? v00 : alpha * v00;
                v01 = v01 > 0.f ? v01 : alpha * v01;
                v10 = v10 > 0.f ? v10 : alpha * v10;
                v11 = v11 > 0.f ? v11 : alpha * v11;
            }
            size_t o0 = (size_t)r0 * N + n0 + cj;
            size_t o1 = (size_t)(r0 + 8) * N + n0 + cj;
            if (EPI == 0) {
                *(float2*)(Cf + o0) = make_float2(v00, v01);
                *(float2*)(Cf + o1) = make_float2(v10, v11);
            } else {
                *(uint32_t*)(Ch + o0) = pkbf(v00, v01);
                *(uint32_t*)(Ch + o1) = pkbf(v10, v11);
                *(uint32_t*)(Cl + o0) = pkbf(rsd(v00), rsd(v01));
                *(uint32_t*)(Cl + o1) = pkbf(rsd(v10), rsd(v11));
            }
        }
    }
}

// --------------------------------------------------------------------------------
extern "C" void kernel_launch(void* const* d_in, const int* in_sizes, int n_in,
                              void* d_out, int out_size)
{
    const float* x    = (const float*)d_in[0];
    const float* nz   = (const float*)d_in[1];
    const float* W1   = (const float*)d_in[2];
    const float* b1   = (const float*)d_in[3];
    const float* a1   = (const float*)d_in[4];
    const float* gm1  = (const float*)d_in[5];
    const float* bt1  = (const float*)d_in[6];
    const float* W2   = (const float*)d_in[7];
    const float* b2   = (const float*)d_in[8];
    const float* W3   = (const float*)d_in[9];
    const float* b3   = (const float*)d_in[10];
    const float* a2   = (const float*)d_in[11];
    const float* gm2  = (const float*)d_in[12];
    const float* bt2  = (const float*)d_in[13];
    const float* W4   = (const float*)d_in[14];
    const float* b4   = (const float*)d_in[15];
    const float* fir  = (const float*)d_in[16];
    float* out = (float*)d_out;

    __nv_bfloat16 *xh, *xl, *h1h, *h1l, *ych, *ycl, *ddh, *ddl;
    __nv_bfloat16 *W1h, *W1l, *W2h, *W2l, *W3h, *W3l, *W4h, *W4l;
    float *y, *b2f, *b4f, *st, *part, *nc;
    cudaGetSymbolAddress((void**)&xh,  g_xh);   cudaGetSymbolAddress((void**)&xl,  g_xl);
    cudaGetSymbolAddress((void**)&h1h, g_h1h);  cudaGetSymbolAddress((void**)&h1l, g_h1l);
    cudaGetSymbolAddress((void**)&y,   g_y);
    cudaGetSymbolAddress((void**)&ych, g_ych);  cudaGetSymbolAddress((void**)&ycl, g_ycl);
    cudaGetSymbolAddress((void**)&ddh, g_ddh);  cudaGetSymbolAddress((void**)&ddl, g_ddl);
    cudaGetSymbolAddress((void**)&W1h, g_W1h);  cudaGetSymbolAddress((void**)&W1l, g_W1l);
    cudaGetSymbolAddress((void**)&W2h, g_W2h);  cudaGetSymbolAddress((void**)&W2l, g_W2l);
    cudaGetSymbolAddress((void**)&W3h, g_W3h);  cudaGetSymbolAddress((void**)&W3l, g_W3l);
    cudaGetSymbolAddress((void**)&W4h, g_W4h);  cudaGetSymbolAddress((void**)&W4l, g_W4l);
    cudaGetSymbolAddress((void**)&b2f, g_b2f);
    cudaGetSymbolAddress((void**)&b4f, g_b4f);
    cudaGetSymbolAddress((void**)&st,  g_stats);
    cudaGetSymbolAddress((void**)&part,g_part);
    cudaGetSymbolAddress((void**)&nc,  g_nc);

    const int SMEM = 1024 + STAGES * STAGE_BYTES;   // 164864 B
    cudaFuncSetAttribute(gemm_mma<0>, cudaFuncAttributeMaxDynamicSharedMemorySize, SMEM);
    cudaFuncSetAttribute(gemm_mma<1>, cudaFuncAttributeMaxDynamicSharedMemorySize, SMEM);

    // 0) independent prep
    splitx_kernel<<<(B_ROWS * BLK / 4 + 255) / 256, 256>>>(x, xh, xl, B_ROWS * BLK / 4);
    split_kernel<<<(BLK * BLK + 255) / 256, 256>>>(W1, W1h, W1l, BLK * BLK);
    split_kernel<<<(BLK * CUN + 255) / 256, 256>>>(W3, W3h, W3l, BLK * CUN);
    noise_kernel<<<1, 256>>>(nz, fir, nc, out + (size_t)B_ROWS * BLK);

    // 1) h1 = prelu(x @ W1^T + b1)  -> bf16 hi/lo
    gemm_mma<1><<<dim3(BLK / NTT, B_ROWS / MT), 256, SMEM>>>(
        xh, xl, W1h, W1l, b1, nullptr, h1h, h1l, B_ROWS, BLK, BLK, a1);

    // 2) BN1 stats + fold into W2
    stats_partial_bf<<<dim3(BLK / 256, B_ROWS / 256), 256>>>(h1h, h1l, part, BLK);
    stats_reduce2<<<BLK, 256>>>(part, st, st + BLK, BLK);
    fold_kernel<<<CUN, 128>>>(W2, b2, gm1, bt1, st, st + BLK, W2h, W2l, b2f, BLK);

    // 3) y = h1_bn @ W2^T + b2 (fp32), then rownorm + noise -> yc hi/lo
    gemm_mma<0><<<dim3(CUN / NTT, B_ROWS / MT), 256, SMEM>>>(
        h1h, h1l, W2h, W2l, b2f, y, nullptr, nullptr, B_ROWS, CUN, BLK, nullptr);
    rownorm_kernel<<<B_ROWS / 8, 256>>>(y, nc, ych, ycl);

    // 4) d = prelu(yc @ W3^T + b3) -> bf16 hi/lo
    gemm_mma<1><<<dim3(BLK / NTT, B_ROWS / MT), 256, SMEM>>>(
        ych, ycl, W3h, W3l, b3, nullptr, ddh, ddl, B_ROWS, BLK, CUN, a2);

    // 5) BN2 stats + fold into W4
    stats_partial_bf<<<dim3(BLK / 256, B_ROWS / 256), 256>>>(ddh, ddl, part, BLK);
    stats_reduce2<<<BLK, 256>>>(part, st + 2 * BLK, st + 3 * BLK, BLK);
    fold_kernel<<<BLK, 128>>>(W4, b4, gm2, bt2, st + 2 * BLK, st + 3 * BLK, W4h, W4l, b4f, BLK);

    // 6) out = d_bn @ W4^T + b4 (fp32)
    gemm_mma<0><<<dim3(BLK / NTT, B_ROWS / MT), 256, SMEM>>>(
        ddh, ddl, W4h, W4l, b4f, out, nullptr, nullptr, B_ROWS, BLK, BLK, nullptr);

    (void)in_sizes; (void)n_in; (void)out_size;
}

// round 8
// speedup vs baseline: 2.1531x; 1.0725x over previous
#include <cuda_runtime.h>
#include <cuda_bf16.h>
#include <math.h>
#include <stdint.h>

#define B_ROWS 65536
#define BLK    512
#define CUN    256
#define TAPSN  100

#define MT     128
#define NTT    256
#define KTT    32
#define STAGES 3
#define RS     40                         // padded SMEM row stride (elems) -> 80 B
// stage layout (elems): Ah[128*RS] Al[128*RS] Bh[256*RS] Bl[256*RS]
#define AH_OFF 0
#define AL_OFF (128 * RS)
#define BH_OFF (256 * RS)
#define BL_OFF (512 * RS)
#define STAGE_ELEMS (768 * RS)
#define STAGE_BYTES (STAGE_ELEMS * 2)     // 61440
#define HDR    4096                       // bias(1K) + nc(1K) + rowred(2K)

// ---------------- device scratch ----------------
static __device__ __nv_bfloat16 g_xh [(size_t)B_ROWS * BLK], g_xl [(size_t)B_ROWS * BLK];
static __device__ __nv_bfloat16 g_h1h[(size_t)B_ROWS * BLK], g_h1l[(size_t)B_ROWS * BLK];
static __device__ __nv_bfloat16 g_ych[(size_t)B_ROWS * CUN], g_ycl[(size_t)B_ROWS * CUN];
static __device__ __nv_bfloat16 g_ddh[(size_t)B_ROWS * BLK], g_ddl[(size_t)B_ROWS * BLK];
static __device__ __nv_bfloat16 g_W1h[BLK * BLK], g_W1l[BLK * BLK];
static __device__ __nv_bfloat16 g_W2h[CUN * BLK], g_W2l[CUN * BLK];
static __device__ __nv_bfloat16 g_W3h[BLK * CUN], g_W3l[BLK * CUN];
static __device__ __nv_bfloat16 g_W4h[BLK * BLK], g_W4l[BLK * BLK];
static __device__ float g_b2f[CUN], g_b4f[BLK];
static __device__ float g_stats[4 * BLK];
static __device__ float g_part [256 * 2 * BLK];
static __device__ float g_nc  [CUN];

// ---------------- helpers ----------------
__device__ __forceinline__ uint32_t s2u(const void* p) {
    return (uint32_t)__cvta_generic_to_shared(p);
}
__device__ __forceinline__ void cpa16(uint32_t d, const void* s) {
    asm volatile("cp.async.cg.shared.global [%0], [%1], 16;" :: "r"(d), "l"(s));
}
__device__ __forceinline__ void ldm4(uint32_t* f, uint32_t a) {
    asm volatile("ldmatrix.sync.aligned.m8n8.x4.shared.b16 {%0,%1,%2,%3}, [%4];"
                 : "=r"(f[0]), "=r"(f[1]), "=r"(f[2]), "=r"(f[3]) : "r"(a));
}
__device__ __forceinline__ void mma_bf(float* d, const uint32_t* a, const uint32_t* b) {
    asm volatile("mma.sync.aligned.m16n8k16.row.col.f32.bf16.bf16.f32 "
                 "{%0,%1,%2,%3}, {%4,%5,%6,%7}, {%8,%9}, {%0,%1,%2,%3};"
                 : "+f"(d[0]), "+f"(d[1]), "+f"(d[2]), "+f"(d[3])
                 : "r"(a[0]), "r"(a[1]), "r"(a[2]), "r"(a[3]), "r"(b[0]), "r"(b[1]));
}
__device__ __forceinline__ uint32_t pkbf(float a, float b) {
    __nv_bfloat162 h = __floats2bfloat162_rn(a, b);
    return *(uint32_t*)&h;
}
__device__ __forceinline__ float rsd(float v) {
    return v - __bfloat162float(__float2bfloat16_rn(v));
}

// ---------------- fused prep: x split | W1 split | W3 split | FIR noise ---------
#define SPLITX_BLOCKS 32768   /* B_ROWS*BLK/4/256 */
#define W1_BLOCKS     1024
#define W3_BLOCKS     512
__global__ void prep_kernel(const float* __restrict__ x,
                            __nv_bfloat16* __restrict__ xh, __nv_bfloat16* __restrict__ xl,
                            const float* __restrict__ W1,
                            __nv_bfloat16* __restrict__ W1h, __nv_bfloat16* __restrict__ W1l,
                            const float* __restrict__ W3,
                            __nv_bfloat16* __restrict__ W3h, __nv_bfloat16* __restrict__ W3l,
                            const float* __restrict__ noise, const float* __restrict__ fir,
                            float* __restrict__ nc, float* __restrict__ out_tail)
{
    int bid = blockIdx.x, tid = threadIdx.x;
    if (bid < SPLITX_BLOCKS) {
        int i = bid * 256 + tid;
        float4 v = ((const float4*)x)[i];
        ((uint2*)xh)[i] = make_uint2(pkbf(v.x, v.y), pkbf(v.z, v.w));
        ((uint2*)xl)[i] = make_uint2(pkbf(rsd(v.x), rsd(v.y)), pkbf(rsd(v.z), rsd(v.w)));
    } else if (bid < SPLITX_BLOCKS + W1_BLOCKS) {
        int i = (bid - SPLITX_BLOCKS) * 256 + tid;
        float v = W1[i];
        __nv_bfloat16 h = __float2bfloat16_rn(v);
        W1h[i] = h;
        W1l[i] = __float2bfloat16_rn(v - __bfloat162float(h));
    } else if (bid < SPLITX_BLOCKS + W1_BLOCKS + W3_BLOCKS) {
        int i = (bid - SPLITX_BLOCKS - W1_BLOCKS) * 256 + tid;
        float v = W3[i];
        __nv_bfloat16 h = __float2bfloat16_rn(v);
        W3h[i] = h;
        W3l[i] = __float2bfloat16_rn(v - __bfloat162float(h));
    } else {
        int i = tid;
        double snr_lin = pow(10.0, 0.7);
        float nstd = (float)sqrt(1.0 / (2.0 * 2.0 * snr_lin));   // rate = 2
        float acc = 0.f;
#pragma unroll 4
        for (int t = 0; t < TAPSN; t++) {
            int idx = i + 49 - t;
            if (idx >= 0 && idx < CUN) acc += fir[t] * (noise[idx] * nstd);
        }
        nc[i] = acc;
        out_tail[i] = acc;
    }
}

// ---------------- BN stats (deterministic two-pass) ------------------------------
__global__ void stats_partial_bf(const __nv_bfloat16* __restrict__ Hh,
                                 const __nv_bfloat16* __restrict__ Hl,
                                 float* __restrict__ part, int Ncols)
{
    int c  = blockIdx.x * 256 + threadIdx.x;
    int r0 = blockIdx.y * 256;
    float s = 0.f, q = 0.f;
#pragma unroll 4
    for (int r = 0; r < 256; r++) {
        size_t idx = (size_t)(r0 + r) * Ncols + c;
        float v = __bfloat162float(Hh[idx]) + __bfloat162float(Hl[idx]);
        s += v; q += v * v;
    }
    part[((size_t)blockIdx.y * 2    ) * Ncols + c] = s;
    part[((size_t)blockIdx.y * 2 + 1) * Ncols + c] = q;
}

__global__ void stats_reduce2(const float* __restrict__ part,
                              float* __restrict__ sum, float* __restrict__ sq, int Ncols)
{
    int c = blockIdx.x;
    int t = threadIdx.x;
    float s = part[((size_t)t * 2    ) * Ncols + c];
    float q = part[((size_t)t * 2 + 1) * Ncols + c];
#pragma unroll
    for (int o = 16; o > 0; o >>= 1) {
        s += __shfl_down_sync(0xFFFFFFFFu, s, o);
        q += __shfl_down_sync(0xFFFFFFFFu, q, o);
    }
    __shared__ float sh[64];
    int w = t >> 5, l = t & 31;
    if (l == 0) { sh[w] = s; sh[32 + w] = q; }
    __syncthreads();
    if (t == 0) {
        float S = 0.f, Q = 0.f;
        for (int i = 0; i < 8; i++) { S += sh[i]; Q += sh[32 + i]; }
        sum[c] = S; sq[c] = Q;
    }
}

__global__ void fold_kernel(const float* __restrict__ Wsrc, const float* __restrict__ bsrc,
                            const float* __restrict__ gam,  const float* __restrict__ bt,
                            const float* __restrict__ sum,  const float* __restrict__ sq,
                            __nv_bfloat16* __restrict__ Whi, __nv_bfloat16* __restrict__ Wlo,
                            float* __restrict__ bdst, int Kin)
{
    int j = blockIdx.x;
    int tid = threadIdx.x;  // 128
    const float invB = 1.0f / (float)B_ROWS;
    float partial = 0.f;
    for (int k = tid; k < Kin; k += 128) {
        float mu  = sum[k] * invB;
        float var = sq[k] * invB - mu * mu;
        float rs  = rsqrtf(var + 1e-5f);
        float s   = gam[k] * rs;
        float w   = Wsrc[(size_t)j * Kin + k];
        float wf  = w * s;
        __nv_bfloat16 h = __float2bfloat16_rn(wf);
        Whi[(size_t)j * Kin + k] = h;
        Wlo[(size_t)j * Kin + k] = __float2bfloat16_rn(wf - __bfloat162float(h));
        partial += w * (bt[k] - mu * s);
    }
    __shared__ float sh[128];
    sh[tid] = partial; __syncthreads();
    for (int s = 64; s > 0; s >>= 1) { if (tid < s) sh[tid] += sh[tid + s]; __syncthreads(); }
    if (tid == 0) bdst[j] = bsrc[j] + sh[0];
}

// ---------------- multistage warp-MMA GEMM, CTA 128x256, warp tile 64x64 ---------
// C = epi(A @ W^T + bias); A=(AH+AL), W=(BH+BL), 3-term bf16 split.
// EPI: 0 fp32 out; 1 PReLU -> bf16 hi/lo; 2 rownorm+noise -> bf16 hi/lo (NT==N).
template <int EPI>
__global__ void __launch_bounds__(256, 1)
gemm_mma(const __nv_bfloat16* __restrict__ AH, const __nv_bfloat16* __restrict__ AL,
         const __nv_bfloat16* __restrict__ BH, const __nv_bfloat16* __restrict__ BL,
         const float* __restrict__ bias,
         float* __restrict__ Cf, __nv_bfloat16* __restrict__ Ch, __nv_bfloat16* __restrict__ Cl,
         int M, int N, int K, const float* __restrict__ alpha_ptr,
         const float* __restrict__ nc)
{
    extern __shared__ char smem[];
    float* bias_s = (float*)smem;              // 256 f
    float* nc_s   = (float*)(smem + 1024);     // 256 f
    float* rsq    = (float*)(smem + 2048);     // 4 x 128 f
    char*  stage0 = smem + HDR;

    const int tid = threadIdx.x;
    const int lane = tid & 31, wid = tid >> 5;
    const int wm = wid & 1, wn = wid >> 1;     // 2 x 4 warps, warp tile 64 x 64
    const int m0 = blockIdx.y * MT, n0 = blockIdx.x * NTT;

    bias_s[tid] = bias[n0 + tid];
    if (EPI == 2) nc_s[tid] = nc[tid];

    float acc[4][8][4];
#pragma unroll
    for (int i = 0; i < 4; i++)
#pragma unroll
        for (int j = 0; j < 8; j++)
#pragma unroll
            for (int r = 0; r < 4; r++) acc[i][j][r] = 0.f;

    const int nit = K / KTT;

    auto load_stage = [&](int s, int k0) {
        uint32_t sb = s2u(stage0 + s * STAGE_BYTES);
#pragma unroll
        for (int i = 0; i < 12; i++) {
            int ch = tid + i * 256;
            int local, r, c;
            uint32_t dst;
            const __nv_bfloat16* g;
            if (i < 2) {                     // Ah: 512 chunks (128 rows x 4)
                local = ch;          r = local >> 2; c = local & 3;
                dst = sb + (AH_OFF + r * RS) * 2 + c * 16;
                g = AH + (size_t)(m0 + r) * K + k0 + c * 8;
            } else if (i < 4) {              // Al
                local = ch - 512;    r = local >> 2; c = local & 3;
                dst = sb + (AL_OFF + r * RS) * 2 + c * 16;
                g = AL + (size_t)(m0 + r) * K + k0 + c * 8;
            } else if (i < 8) {              // Bh: 1024 chunks (256 rows x 4)
                local = ch - 1024;   r = local >> 2; c = local & 3;
                dst = sb + (BH_OFF + r * RS) * 2 + c * 16;
                g = BH + (size_t)(n0 + r) * K + k0 + c * 8;
            } else {                         // Bl
                local = ch - 2048;   r = local >> 2; c = local & 3;
                dst = sb + (BL_OFF + r * RS) * 2 + c * 16;
                g = BL + (size_t)(n0 + r) * K + k0 + c * 8;
            }
            cpa16(dst, g);
        }
    };

    for (int s = 0; s < STAGES - 1; s++) {
        if (s < nit) load_stage(s, s * KTT);
        asm volatile("cp.async.commit_group;" ::: "memory");
    }

    const uint32_t aoff = (uint32_t)(((wm * 64 + (lane & 15)) * RS + (lane >> 4) * 8) * 2);
    const uint32_t boff = (uint32_t)(((wn * 64 + (lane & 7) + ((lane >> 4) << 3)) * RS
                                      + ((lane >> 3) & 1) * 8) * 2);

    for (int it = 0; it < nit; it++) {
        asm volatile("cp.async.wait_group 1;" ::: "memory");
        __syncthreads();
        int ns = it + STAGES - 1;
        if (ns < nit) load_stage(ns % STAGES, ns * KTT);
        asm volatile("cp.async.commit_group;" ::: "memory");

        uint32_t sb = s2u(stage0 + (it % STAGES) * STAGE_BYTES);
#pragma unroll
        for (int k16 = 0; k16 < 2; k16++) {
            uint32_t ko = k16 * 32;   // 16 bf16 = 32 B
            uint32_t ah[4][4], bh[8][2];
#pragma unroll
            for (int i = 0; i < 4; i++)
                ldm4(ah[i], sb + AH_OFF * 2 + aoff + i * 16 * RS * 2 + ko);
#pragma unroll
            for (int p = 0; p < 4; p++) {
                uint32_t t[4];
                ldm4(t, sb + BH_OFF * 2 + boff + p * 16 * RS * 2 + ko);
                bh[p*2][0] = t[0]; bh[p*2][1] = t[1]; bh[p*2+1][0] = t[2]; bh[p*2+1][1] = t[3];
            }
#pragma unroll
            for (int i = 0; i < 4; i++)
#pragma unroll
                for (int j = 0; j < 8; j++) mma_bf(acc[i][j], ah[i], bh[j]);

            uint32_t bl[8][2];
#pragma unroll
            for (int p = 0; p < 4; p++) {
                uint32_t t[4];
                ldm4(t, sb + BL_OFF * 2 + boff + p * 16 * RS * 2 + ko);
                bl[p*2][0] = t[0]; bl[p*2][1] = t[1]; bl[p*2+1][0] = t[2]; bl[p*2+1][1] = t[3];
            }
#pragma unroll
            for (int i = 0; i < 4; i++)
#pragma unroll
                for (int j = 0; j < 8; j++) mma_bf(acc[i][j], ah[i], bl[j]);

            uint32_t al[4][4];
#pragma unroll
            for (int i = 0; i < 4; i++)
                ldm4(al[i], sb + AL_OFF * 2 + aoff + i * 16 * RS * 2 + ko);
#pragma unroll
            for (int i = 0; i < 4; i++)
#pragma unroll
                for (int j = 0; j < 8; j++) mma_bf(acc[i][j], al[i], bh[j]);
        }
    }

    // -------- epilogue --------
    const int qr = lane >> 2, qc = (lane & 3) * 2;

    // add bias (all EPI)
#pragma unroll
    for (int i = 0; i < 4; i++)
#pragma unroll
        for (int j = 0; j < 8; j++) {
            int cj = wn * 64 + j * 8 + qc;
            acc[i][j][0] += bias_s[cj];     acc[i][j][1] += bias_s[cj + 1];
            acc[i][j][2] += bias_s[cj];     acc[i][j][3] += bias_s[cj + 1];
        }

    if (EPI == 2) {
        // deterministic per-row sum of squares: shfl over quad-columns, smem over wn
#pragma unroll
        for (int i = 0; i < 4; i++) {
            float s0 = 0.f, s1 = 0.f;
#pragma unroll
            for (int j = 0; j < 8; j++) {
                s0 += acc[i][j][0] * acc[i][j][0] + acc[i][j][1] * acc[i][j][1];
                s1 += acc[i][j][2] * acc[i][j][2] + acc[i][j][3] * acc[i][j][3];
            }
            s0 += __shfl_xor_sync(0xFFFFFFFFu, s0, 1);
            s0 += __shfl_xor_sync(0xFFFFFFFFu, s0, 2);
            s1 += __shfl_xor_sync(0xFFFFFFFFu, s1, 1);
            s1 += __shfl_xor_sync(0xFFFFFFFFu, s1, 2);
            if ((lane & 3) == 0) {
                int rl = wm * 64 + i * 16 + qr;
                rsq[wn * 128 + rl]     = s0;
                rsq[wn * 128 + rl + 8] = s1;
            }
        }
        __syncthreads();
#pragma unroll
        for (int i = 0; i < 4; i++) {
            int rl = wm * 64 + i * 16 + qr;
            float t0 = rsq[rl]       + rsq[128 + rl]     + rsq[256 + rl]     + rsq[384 + rl];
            float t1 = rsq[rl + 8]   + rsq[128 + rl + 8] + rsq[256 + rl + 8] + rsq[384 + rl + 8];
            float sc0 = 16.0f * rsqrtf(t0);   // sqrt(CU) = 16
            float sc1 = 16.0f * rsqrtf(t1);
            size_t r0 = (size_t)(m0 + rl);
#pragma unroll
            for (int j = 0; j < 8; j++) {
                int cj = wn * 64 + j * 8 + qc;
                float u00 = acc[i][j][0] * sc0 + nc_s[cj];
                float u01 = acc[i][j][1] * sc0 + nc_s[cj + 1];
                float u10 = acc[i][j][2] * sc1 + nc_s[cj];
                float u11 = acc[i][j][3] * sc1 + nc_s[cj + 1];
                size_t o0 = r0 * N + n0 + cj;
                size_t o1 = (r0 + 8) * N + n0 + cj;
                *(uint32_t*)(Ch + o0) = pkbf(u00, u01);
                *(uint32_t*)(Ch + o1) = pkbf(u10, u11);
                *(uint32_t*)(Cl + o0) = pkbf(rsd(u00), rsd(u01));
                *(uint32_t*)(Cl + o1) = pkbf(rsd(u10), rsd(u11));
            }
        }
    } else {
        float alpha = (EPI == 1) ? *alpha_ptr : 0.f;
#pragma unroll
        for (int i = 0; i < 4; i++) {
            int rl = wm * 64 + i * 16 + qr;
            size_t r0 = (size_t)(m0 + rl);
#pragma unroll
            for (int j = 0; j < 8; j++) {
                int cj = wn * 64 + j * 8 + qc;
                float v00 = acc[i][j][0], v01 = acc[i][j][1];
                float v10 = acc[i][j][2], v11 = acc[i][j][3];
                if (EPI == 1) {
                    v00 = v00 > 0.f ? v00 : alpha * v00;
                    v01 = v01 > 0.f ? v01 : alpha * v01;
                    v10 = v10 > 0.f ? v10 : alpha * v10;
                    v11 = v11 > 0.f ? v11 : alpha * v11;
                }
                size_t o0 = r0 * N + n0 + cj;
                size_t o1 = (r0 + 8) * N + n0 + cj;
                if (EPI == 0) {
                    *(float2*)(Cf + o0) = make_float2(v00, v01);
                    *(float2*)(Cf + o1) = make_float2(v10, v11);
                } else {
                    *(uint32_t*)(Ch + o0) = pkbf(v00, v01);
                    *(uint32_t*)(Ch + o1) = pkbf(v10, v11);
                    *(uint32_t*)(Cl + o0) = pkbf(rsd(v00), rsd(v01));
                    *(uint32_t*)(Cl + o1) = pkbf(rsd(v10), rsd(v11));
                }
            }
        }
    }
}

// --------------------------------------------------------------------------------
extern "C" void kernel_launch(void* const* d_in, const int* in_sizes, int n_in,
                              void* d_out, int out_size)
{
    const float* x    = (const float*)d_in[0];
    const float* nz   = (const float*)d_in[1];
    const float* W1   = (const float*)d_in[2];
    const float* b1   = (const float*)d_in[3];
    const float* a1   = (const float*)d_in[4];
    const float* gm1  = (const float*)d_in[5];
    const float* bt1  = (const float*)d_in[6];
    const float* W2   = (const float*)d_in[7];
    const float* b2   = (const float*)d_in[8];
    const float* W3   = (const float*)d_in[9];
    const float* b3   = (const float*)d_in[10];
    const float* a2   = (const float*)d_in[11];
    const float* gm2  = (const float*)d_in[12];
    const float* bt2  = (const float*)d_in[13];
    const float* W4   = (const float*)d_in[14];
    const float* b4   = (const float*)d_in[15];
    const float* fir  = (const float*)d_in[16];
    float* out = (float*)d_out;

    __nv_bfloat16 *xh, *xl, *h1h, *h1l, *ych, *ycl, *ddh, *ddl;
    __nv_bfloat16 *W1h, *W1l, *W2h, *W2l, *W3h, *W3l, *W4h, *W4l;
    float *b2f, *b4f, *st, *part, *nc;
    cudaGetSymbolAddress((void**)&xh,  g_xh);   cudaGetSymbolAddress((void**)&xl,  g_xl);
    cudaGetSymbolAddress((void**)&h1h, g_h1h);  cudaGetSymbolAddress((void**)&h1l, g_h1l);
    cudaGetSymbolAddress((void**)&ych, g_ych);  cudaGetSymbolAddress((void**)&ycl, g_ycl);
    cudaGetSymbolAddress((void**)&ddh, g_ddh);  cudaGetSymbolAddress((void**)&ddl, g_ddl);
    cudaGetSymbolAddress((void**)&W1h, g_W1h);  cudaGetSymbolAddress((void**)&W1l, g_W1l);
    cudaGetSymbolAddress((void**)&W2h, g_W2h);  cudaGetSymbolAddress((void**)&W2l, g_W2l);
    cudaGetSymbolAddress((void**)&W3h, g_W3h);  cudaGetSymbolAddress((void**)&W3l, g_W3l);
    cudaGetSymbolAddress((void**)&W4h, g_W4h);  cudaGetSymbolAddress((void**)&W4l, g_W4l);
    cudaGetSymbolAddress((void**)&b2f, g_b2f);
    cudaGetSymbolAddress((void**)&b4f, g_b4f);
    cudaGetSymbolAddress((void**)&st,  g_stats);
    cudaGetSymbolAddress((void**)&part,g_part);
    cudaGetSymbolAddress((void**)&nc,  g_nc);

    const int SMEM = HDR + STAGES * STAGE_BYTES;   // 188416
    cudaFuncSetAttribute(gemm_mma<0>, cudaFuncAttributeMaxDynamicSharedMemorySize, SMEM);
    cudaFuncSetAttribute(gemm_mma<1>, cudaFuncAttributeMaxDynamicSharedMemorySize, SMEM);
    cudaFuncSetAttribute(gemm_mma<2>, cudaFuncAttributeMaxDynamicSharedMemorySize, SMEM);

    // 0) fused prep (x split + W1/W3 splits + FIR noise)
    prep_kernel<<<SPLITX_BLOCKS + W1_BLOCKS + W3_BLOCKS + 1, 256>>>(
        x, xh, xl, W1, W1h, W1l, W3, W3h, W3l, nz, fir, nc,
        out + (size_t)B_ROWS * BLK);

    // 1) h1 = prelu(x @ W1^T + b1) -> bf16 hi/lo
    gemm_mma<1><<<dim3(BLK / NTT, B_ROWS / MT), 256, SMEM>>>(
        xh, xl, W1h, W1l, b1, nullptr, h1h, h1l, B_ROWS, BLK, BLK, a1, nullptr);

    // 2) BN1 stats + fold into W2
    stats_partial_bf<<<dim3(BLK / 256, B_ROWS / 256), 256>>>(h1h, h1l, part, BLK);
    stats_reduce2<<<BLK, 256>>>(part, st, st + BLK, BLK);
    fold_kernel<<<CUN, 128>>>(W2, b2, gm1, bt1, st, st + BLK, W2h, W2l, b2f, BLK);

    // 3) yc = 16*(h1_bn @ W2^T + b2)/||row|| + noise -> bf16 hi/lo (fused epilogue)
    gemm_mma<2><<<dim3(1, B_ROWS / MT), 256, SMEM>>>(
        h1h, h1l, W2h, W2l, b2f, nullptr, ych, ycl, B_ROWS, CUN, BLK, nullptr, nc);

    // 4) d = prelu(yc @ W3^T + b3) -> bf16 hi/lo
    gemm_mma<1><<<dim3(BLK / NTT, B_ROWS / MT), 256, SMEM>>>(
        ych, ycl, W3h, W3l, b3, nullptr, ddh, ddl, B_ROWS, BLK, CUN, a2, nullptr);

    // 5) BN2 stats + fold into W4
    stats_partial_bf<<<dim3(BLK / 256, B_ROWS / 256), 256>>>(ddh, ddl, part, BLK);
    stats_reduce2<<<BLK, 256>>>(part, st + 2 * BLK, st + 3 * BLK, BLK);
    fold_kernel<<<BLK, 128>>>(W4, b4, gm2, bt2, st + 2 * BLK, st + 3 * BLK, W4h, W4l, b4f, BLK);

    // 6) out = d_bn @ W4^T + b4 (fp32)
    gemm_mma<0><<<dim3(BLK / NTT, B_ROWS / MT), 256, SMEM>>>(
        ddh, ddl, W4h, W4l, b4f, out, nullptr, nullptr, B_ROWS, BLK, BLK, nullptr, nullptr);

    (void)in_sizes; (void)n_in; (void)out_size;
}

// round 9
// speedup vs baseline: 2.3174x; 1.0763x over previous
#include <cuda_runtime.h>
#include <cuda_bf16.h>
#include <math.h>
#include <stdint.h>

#define B_ROWS 65536
#define BLK    512
#define CUN    256
#define TAPSN  100

#define KTT    32
#define STAGES 3
#define RS     40                         // padded SMEM row stride (elems) -> 80 B

// ---- shape A (main GEMMs): CTA 256x128, 512 thr, warp 64x32 ----
#define A_CM 256
#define A_CN 128
#define A_AH 0
#define A_AL (256 * RS)
#define A_BH (512 * RS)
#define A_BL (640 * RS)
#define A_STAGE_B (768 * RS * 2)          // 61440
#define A_HDR 8192                        // bias(512) | s_sm(2K @1024) | q_sm(2K @3072)

// ---- shape B (G2, rownorm): CTA 128x256, 256 thr, warp 64x64 ----
#define B_AH 0
#define B_AL (128 * RS)
#define B_BH (256 * RS)
#define B_BL (512 * RS)
#define B_STAGE_B (768 * RS * 2)
#define B_HDR 4096

// ---------------- device scratch ----------------
static __device__ __nv_bfloat16 g_xh [(size_t)B_ROWS * BLK], g_xl [(size_t)B_ROWS * BLK];
static __device__ __nv_bfloat16 g_h1h[(size_t)B_ROWS * BLK], g_h1l[(size_t)B_ROWS * BLK];
static __device__ __nv_bfloat16 g_ych[(size_t)B_ROWS * CUN], g_ycl[(size_t)B_ROWS * CUN];
static __device__ __nv_bfloat16 g_ddh[(size_t)B_ROWS * BLK], g_ddl[(size_t)B_ROWS * BLK];
static __device__ __nv_bfloat16 g_W1h[BLK * BLK], g_W1l[BLK * BLK];
static __device__ __nv_bfloat16 g_W2h[CUN * BLK], g_W2l[CUN * BLK];
static __device__ __nv_bfloat16 g_W3h[BLK * CUN], g_W3l[BLK * CUN];
static __device__ __nv_bfloat16 g_W4h[BLK * BLK], g_W4l[BLK * BLK];
static __device__ float g_b2f[CUN], g_b4f[BLK];
static __device__ float g_stats[4 * BLK];
static __device__ float g_part [256 * 2 * BLK];   // [mblock][2][512]
static __device__ float g_nc  [CUN];

// ---------------- helpers ----------------
__device__ __forceinline__ uint32_t s2u(const void* p) {
    return (uint32_t)__cvta_generic_to_shared(p);
}
__device__ __forceinline__ void cpa16(uint32_t d, const void* s) {
    asm volatile("cp.async.cg.shared.global [%0], [%1], 16;" :: "r"(d), "l"(s));
}
__device__ __forceinline__ void ldm4(uint32_t* f, uint32_t a) {
    asm volatile("ldmatrix.sync.aligned.m8n8.x4.shared.b16 {%0,%1,%2,%3}, [%4];"
                 : "=r"(f[0]), "=r"(f[1]), "=r"(f[2]), "=r"(f[3]) : "r"(a));
}
__device__ __forceinline__ void mma_bf(float* d, const uint32_t* a, const uint32_t* b) {
    asm volatile("mma.sync.aligned.m16n8k16.row.col.f32.bf16.bf16.f32 "
                 "{%0,%1,%2,%3}, {%4,%5,%6,%7}, {%8,%9}, {%0,%1,%2,%3};"
                 : "+f"(d[0]), "+f"(d[1]), "+f"(d[2]), "+f"(d[3])
                 : "r"(a[0]), "r"(a[1]), "r"(a[2]), "r"(a[3]), "r"(b[0]), "r"(b[1]));
}
__device__ __forceinline__ uint32_t pkbf(float a, float b) {
    __nv_bfloat162 h = __floats2bfloat162_rn(a, b);
    return *(uint32_t*)&h;
}
__device__ __forceinline__ float rsd(float v) {
    return v - __bfloat162float(__float2bfloat16_rn(v));
}

// ---------------- fused prep: x split | W1 split | W3 split | FIR noise ---------
#define SPLITX_BLOCKS 32768
#define W1_BLOCKS     1024
#define W3_BLOCKS     512
__global__ void prep_kernel(const float* __restrict__ x,
                            __nv_bfloat16* __restrict__ xh, __nv_bfloat16* __restrict__ xl,
                            const float* __restrict__ W1,
                            __nv_bfloat16* __restrict__ W1h, __nv_bfloat16* __restrict__ W1l,
                            const float* __restrict__ W3,
                            __nv_bfloat16* __restrict__ W3h, __nv_bfloat16* __restrict__ W3l,
                            const float* __restrict__ noise, const float* __restrict__ fir,
                            float* __restrict__ nc, float* __restrict__ out_tail)
{
    int bid = blockIdx.x, tid = threadIdx.x;
    if (bid < SPLITX_BLOCKS) {
        int i = bid * 256 + tid;
        float4 v = ((const float4*)x)[i];
        ((uint2*)xh)[i] = make_uint2(pkbf(v.x, v.y), pkbf(v.z, v.w));
        ((uint2*)xl)[i] = make_uint2(pkbf(rsd(v.x), rsd(v.y)), pkbf(rsd(v.z), rsd(v.w)));
    } else if (bid < SPLITX_BLOCKS + W1_BLOCKS) {
        int i = (bid - SPLITX_BLOCKS) * 256 + tid;
        float v = W1[i];
        __nv_bfloat16 h = __float2bfloat16_rn(v);
        W1h[i] = h;
        W1l[i] = __float2bfloat16_rn(v - __bfloat162float(h));
    } else if (bid < SPLITX_BLOCKS + W1_BLOCKS + W3_BLOCKS) {
        int i = (bid - SPLITX_BLOCKS - W1_BLOCKS) * 256 + tid;
        float v = W3[i];
        __nv_bfloat16 h = __float2bfloat16_rn(v);
        W3h[i] = h;
        W3l[i] = __float2bfloat16_rn(v - __bfloat162float(h));
    } else {
        int i = tid;
        double snr_lin = pow(10.0, 0.7);
        float nstd = (float)sqrt(1.0 / (2.0 * 2.0 * snr_lin));   // rate = 2
        float acc = 0.f;
#pragma unroll 4
        for (int t = 0; t < TAPSN; t++) {
            int idx = i + 49 - t;
            if (idx >= 0 && idx < CUN) acc += fir[t] * (noise[idx] * nstd);
        }
        nc[i] = acc;
        out_tail[i] = acc;
    }
}

__global__ void stats_reduce2(const float* __restrict__ part,
                              float* __restrict__ sum, float* __restrict__ sq, int Ncols)
{
    int c = blockIdx.x;
    int t = threadIdx.x;
    float s = part[((size_t)t * 2    ) * Ncols + c];
    float q = part[((size_t)t * 2 + 1) * Ncols + c];
#pragma unroll
    for (int o = 16; o > 0; o >>= 1) {
        s += __shfl_down_sync(0xFFFFFFFFu, s, o);
        q += __shfl_down_sync(0xFFFFFFFFu, q, o);
    }
    __shared__ float sh[64];
    int w = t >> 5, l = t & 31;
    if (l == 0) { sh[w] = s; sh[32 + w] = q; }
    __syncthreads();
    if (t == 0) {
        float S = 0.f, Q = 0.f;
        for (int i = 0; i < 8; i++) { S += sh[i]; Q += sh[32 + i]; }
        sum[c] = S; sq[c] = Q;
    }
}

__global__ void fold_kernel(const float* __restrict__ Wsrc, const float* __restrict__ bsrc,
                            const float* __restrict__ gam,  const float* __restrict__ bt,
                            const float* __restrict__ sum,  const float* __restrict__ sq,
                            __nv_bfloat16* __restrict__ Whi, __nv_bfloat16* __restrict__ Wlo,
                            float* __restrict__ bdst, int Kin)
{
    int j = blockIdx.x;
    int tid = threadIdx.x;  // 128
    const float invB = 1.0f / (float)B_ROWS;
    float partial = 0.f;
    for (int k = tid; k < Kin; k += 128) {
        float mu  = sum[k] * invB;
        float var = sq[k] * invB - mu * mu;
        float rs  = rsqrtf(var + 1e-5f);
        float s   = gam[k] * rs;
        float w   = Wsrc[(size_t)j * Kin + k];
        float wf  = w * s;
        __nv_bfloat16 h = __float2bfloat16_rn(wf);
        Whi[(size_t)j * Kin + k] = h;
        Wlo[(size_t)j * Kin + k] = __float2bfloat16_rn(wf - __bfloat162float(h));
        partial += w * (bt[k] - mu * s);
    }
    __shared__ float sh[128];
    sh[tid] = partial; __syncthreads();
    for (int s = 64; s > 0; s >>= 1) { if (tid < s) sh[tid] += sh[tid + s]; __syncthreads(); }
    if (tid == 0) bdst[j] = bsrc[j] + sh[0];
}

// ================= shape A: CTA 256x128, 512 thr, 16 warps (4x4), warp 64x32 =====
// EPI: 0 -> fp32 out; 1 -> PReLU -> bf16 hi/lo out. STATS: write per-CTA column
// partial sums/squares (post-epilogue values) to part[blockIdx.y][2][N].
template <int EPI, bool STATS>
__global__ void __launch_bounds__(512, 1)
gemm_a(const __nv_bfloat16* __restrict__ AH, const __nv_bfloat16* __restrict__ AL,
       const __nv_bfloat16* __restrict__ BH, const __nv_bfloat16* __restrict__ BL,
       const float* __restrict__ bias,
       float* __restrict__ Cf, __nv_bfloat16* __restrict__ Ch, __nv_bfloat16* __restrict__ Cl,
       int M, int N, int K, const float* __restrict__ alpha_ptr,
       float* __restrict__ part)
{
    extern __shared__ char smem[];
    float* bias_s = (float*)smem;                 // 128 f
    float* s_sm   = (float*)(smem + 1024);        // 4 x 128
    float* q_sm   = (float*)(smem + 3072);        // 4 x 128
    char*  stage0 = smem + A_HDR;

    const int tid = threadIdx.x;
    const int lane = tid & 31, wid = tid >> 5;
    const int wm = wid & 3, wn = wid >> 2;        // 4 x 4 warps, tile 64 x 32
    const int m0 = blockIdx.y * A_CM, n0 = blockIdx.x * A_CN;

    if (tid < A_CN) bias_s[tid] = bias[n0 + tid];

    float acc[4][4][4];
#pragma unroll
    for (int i = 0; i < 4; i++)
#pragma unroll
        for (int j = 0; j < 4; j++)
#pragma unroll
            for (int r = 0; r < 4; r++) acc[i][j][r] = 0.f;

    const int nit = K / KTT;

    auto load_stage = [&](int s, int k0) {
        uint32_t sb = s2u(stage0 + s * A_STAGE_B);
#pragma unroll
        for (int i = 0; i < 6; i++) {
            int ch = tid + i * 512;
            uint32_t dst; const __nv_bfloat16* g;
            if (ch < 1024) {
                int r = ch >> 2, c = ch & 3;
                dst = sb + (A_AH + r * RS) * 2 + c * 16;
                g = AH + (size_t)(m0 + r) * K + k0 + c * 8;
            } else if (ch < 2048) {
                int l = ch - 1024; int r = l >> 2, c = l & 3;
                dst = sb + (A_AL + r * RS) * 2 + c * 16;
                g = AL + (size_t)(m0 + r) * K + k0 + c * 8;
            } else if (ch < 2560) {
                int l = ch - 2048; int r = l >> 2, c = l & 3;
                dst = sb + (A_BH + r * RS) * 2 + c * 16;
                g = BH + (size_t)(n0 + r) * K + k0 + c * 8;
            } else {
                int l = ch - 2560; int r = l >> 2, c = l & 3;
                dst = sb + (A_BL + r * RS) * 2 + c * 16;
                g = BL + (size_t)(n0 + r) * K + k0 + c * 8;
            }
            cpa16(dst, g);
        }
    };

    for (int s = 0; s < STAGES - 1; s++) {
        if (s < nit) load_stage(s, s * KTT);
        asm volatile("cp.async.commit_group;" ::: "memory");
    }

    const uint32_t aoff = (uint32_t)(((wm * 64 + (lane & 15)) * RS + (lane >> 4) * 8) * 2);
    const uint32_t boff = (uint32_t)(((wn * 32 + (lane & 7) + ((lane >> 4) << 3)) * RS
                                      + ((lane >> 3) & 1) * 8) * 2);

    for (int it = 0; it < nit; it++) {
        asm volatile("cp.async.wait_group 1;" ::: "memory");
        __syncthreads();
        int ns = it + STAGES - 1;
        if (ns < nit) load_stage(ns % STAGES, ns * KTT);
        asm volatile("cp.async.commit_group;" ::: "memory");

        uint32_t sb = s2u(stage0 + (it % STAGES) * A_STAGE_B);
#pragma unroll
        for (int k16 = 0; k16 < 2; k16++) {
            uint32_t ko = k16 * 32;
            uint32_t ah[4][4], b0[4][2];
#pragma unroll
            for (int i = 0; i < 4; i++)
                ldm4(ah[i], sb + A_AH * 2 + aoff + i * 16 * RS * 2 + ko);
#pragma unroll
            for (int p = 0; p < 2; p++) {
                uint32_t t[4];
                ldm4(t, sb + A_BH * 2 + boff + p * 16 * RS * 2 + ko);
                b0[p*2][0] = t[0]; b0[p*2][1] = t[1]; b0[p*2+1][0] = t[2]; b0[p*2+1][1] = t[3];
            }
#pragma unroll
            for (int i = 0; i < 4; i++)
#pragma unroll
                for (int j = 0; j < 4; j++) mma_bf(acc[i][j], ah[i], b0[j]);

            uint32_t b1[4][2];
#pragma unroll
            for (int p = 0; p < 2; p++) {
                uint32_t t[4];
                ldm4(t, sb + A_BL * 2 + boff + p * 16 * RS * 2 + ko);
                b1[p*2][0] = t[0]; b1[p*2][1] = t[1]; b1[p*2+1][0] = t[2]; b1[p*2+1][1] = t[3];
            }
#pragma unroll
            for (int i = 0; i < 4; i++)
#pragma unroll
                for (int j = 0; j < 4; j++) mma_bf(acc[i][j], ah[i], b1[j]);

            uint32_t al[4][4];
#pragma unroll
            for (int i = 0; i < 4; i++)
                ldm4(al[i], sb + A_AL * 2 + aoff + i * 16 * RS * 2 + ko);
#pragma unroll
            for (int i = 0; i < 4; i++)
#pragma unroll
                for (int j = 0; j < 4; j++) mma_bf(acc[i][j], al[i], b0[j]);
        }
    }

    // -------- epilogue --------
    const int qr = lane >> 2, qc = (lane & 3) * 2;
    float alpha = (EPI == 1) ? *alpha_ptr : 0.f;
    float cs0[4], cs1[4], cq0[4], cq1[4];
    if (STATS)
#pragma unroll
        for (int j = 0; j < 4; j++) { cs0[j] = cs1[j] = cq0[j] = cq1[j] = 0.f; }

#pragma unroll
    for (int i = 0; i < 4; i++) {
        int rl = wm * 64 + i * 16 + qr;
        size_t r0 = (size_t)(m0 + rl);
#pragma unroll
        for (int j = 0; j < 4; j++) {
            int cj = wn * 32 + j * 8 + qc;
            float b0 = bias_s[cj], b1 = bias_s[cj + 1];
            float v00 = acc[i][j][0] + b0, v01 = acc[i][j][1] + b1;
            float v10 = acc[i][j][2] + b0, v11 = acc[i][j][3] + b1;
            if (EPI == 1) {
                v00 = v00 > 0.f ? v00 : alpha * v00;
                v01 = v01 > 0.f ? v01 : alpha * v01;
                v10 = v10 > 0.f ? v10 : alpha * v10;
                v11 = v11 > 0.f ? v11 : alpha * v11;
            }
            if (STATS) {
                cs0[j] += v00 + v10;  cq0[j] += v00 * v00 + v10 * v10;
                cs1[j] += v01 + v11;  cq1[j] += v01 * v01 + v11 * v11;
            }
            size_t o0 = r0 * N + n0 + cj;
            size_t o1 = (r0 + 8) * N + n0 + cj;
            if (EPI == 0) {
                *(float2*)(Cf + o0) = make_float2(v00, v01);
                *(float2*)(Cf + o1) = make_float2(v10, v11);
            } else {
                *(uint32_t*)(Ch + o0) = pkbf(v00, v01);
                *(uint32_t*)(Ch + o1) = pkbf(v10, v11);
                *(uint32_t*)(Cl + o0) = pkbf(rsd(v00), rsd(v01));
                *(uint32_t*)(Cl + o1) = pkbf(rsd(v10), rsd(v11));
            }
        }
    }

    if (STATS) {
        // reduce over the 8 quad-rows (lanes sharing lane&3), deterministic order
#pragma unroll
        for (int j = 0; j < 4; j++) {
#pragma unroll
            for (int o = 4; o <= 16; o <<= 1) {
                cs0[j] += __shfl_xor_sync(0xFFFFFFFFu, cs0[j], o);
                cs1[j] += __shfl_xor_sync(0xFFFFFFFFu, cs1[j], o);
                cq0[j] += __shfl_xor_sync(0xFFFFFFFFu, cq0[j], o);
                cq1[j] += __shfl_xor_sync(0xFFFFFFFFu, cq1[j], o);
            }
        }
        if (lane < 4) {
#pragma unroll
            for (int j = 0; j < 4; j++) {
                int cj = wn * 32 + j * 8 + lane * 2;
                s_sm[wm * 128 + cj]     = cs0[j];
                s_sm[wm * 128 + cj + 1] = cs1[j];
                q_sm[wm * 128 + cj]     = cq0[j];
                q_sm[wm * 128 + cj + 1] = cq1[j];
            }
        }
        __syncthreads();
        if (tid < 128) {
            float S = s_sm[tid] + s_sm[128 + tid] + s_sm[256 + tid] + s_sm[384 + tid];
            float Q = q_sm[tid] + q_sm[128 + tid] + q_sm[256 + tid] + q_sm[384 + tid];
            part[((size_t)blockIdx.y * 2    ) * N + n0 + tid] = S;
            part[((size_t)blockIdx.y * 2 + 1) * N + n0 + tid] = Q;
        }
    }
}

// ================= shape B (G2): CTA 128x256, 256 thr, rownorm+noise epilogue ====
__global__ void __launch_bounds__(256, 1)
gemm_b(const __nv_bfloat16* __restrict__ AH, const __nv_bfloat16* __restrict__ AL,
       const __nv_bfloat16* __restrict__ BH, const __nv_bfloat16* __restrict__ BL,
       const float* __restrict__ bias,
       __nv_bfloat16* __restrict__ Ch, __nv_bfloat16* __restrict__ Cl,
       int M, int N, int K, const float* __restrict__ nc)
{
    extern __shared__ char smem[];
    float* bias_s = (float*)smem;
    float* nc_s   = (float*)(smem + 1024);
    float* rsq    = (float*)(smem + 2048);
    char*  stage0 = smem + B_HDR;

    const int tid = threadIdx.x;
    const int lane = tid & 31, wid = tid >> 5;
    const int wm = wid & 1, wn = wid >> 1;
    const int m0 = blockIdx.y * 128, n0 = 0;

    bias_s[tid] = bias[tid];
    nc_s[tid] = nc[tid];

    float acc[4][8][4];
#pragma unroll
    for (int i = 0; i < 4; i++)
#pragma unroll
        for (int j = 0; j < 8; j++)
#pragma unroll
            for (int r = 0; r < 4; r++) acc[i][j][r] = 0.f;

    const int nit = K / KTT;

    auto load_stage = [&](int s, int k0) {
        uint32_t sb = s2u(stage0 + s * B_STAGE_B);
#pragma unroll
        for (int i = 0; i < 12; i++) {
            int ch = tid + i * 256;
            uint32_t dst; const __nv_bfloat16* g;
            if (ch < 512) {
                int r = ch >> 2, c = ch & 3;
                dst = sb + (B_AH + r * RS) * 2 + c * 16;
                g = AH + (size_t)(m0 + r) * K + k0 + c * 8;
            } else if (ch < 1024) {
                int l = ch - 512; int r = l >> 2, c = l & 3;
                dst = sb + (B_AL + r * RS) * 2 + c * 16;
                g = AL + (size_t)(m0 + r) * K + k0 + c * 8;
            } else if (ch < 2048) {
                int l = ch - 1024; int r = l >> 2, c = l & 3;
                dst = sb + (B_BH + r * RS) * 2 + c * 16;
                g = BH + (size_t)(n0 + r) * K + k0 + c * 8;
            } else {
                int l = ch - 2048; int r = l >> 2, c = l & 3;
                dst = sb + (B_BL + r * RS) * 2 + c * 16;
                g = BL + (size_t)(n0 + r) * K + k0 + c * 8;
            }
            cpa16(dst, g);
        }
    };

    for (int s = 0; s < STAGES - 1; s++) {
        if (s < nit) load_stage(s, s * KTT);
        asm volatile("cp.async.commit_group;" ::: "memory");
    }

    const uint32_t aoff = (uint32_t)(((wm * 64 + (lane & 15)) * RS + (lane >> 4) * 8) * 2);
    const uint32_t boff = (uint32_t)(((wn * 64 + (lane & 7) + ((lane >> 4) << 3)) * RS
                                      + ((lane >> 3) & 1) * 8) * 2);

    for (int it = 0; it < nit; it++) {
        asm volatile("cp.async.wait_group 1;" ::: "memory");
        __syncthreads();
        int ns = it + STAGES - 1;
        if (ns < nit) load_stage(ns % STAGES, ns * KTT);
        asm volatile("cp.async.commit_group;" ::: "memory");

        uint32_t sb = s2u(stage0 + (it % STAGES) * B_STAGE_B);
#pragma unroll
        for (int k16 = 0; k16 < 2; k16++) {
            uint32_t ko = k16 * 32;
            uint32_t ah[4][4], bh[8][2];
#pragma unroll
            for (int i = 0; i < 4; i++)
                ldm4(ah[i], sb + B_AH * 2 + aoff + i * 16 * RS * 2 + ko);
#pragma unroll
            for (int p = 0; p < 4; p++) {
                uint32_t t[4];
                ldm4(t, sb + B_BH * 2 + boff + p * 16 * RS * 2 + ko);
                bh[p*2][0] = t[0]; bh[p*2][1] = t[1]; bh[p*2+1][0] = t[2]; bh[p*2+1][1] = t[3];
            }
#pragma unroll
            for (int i = 0; i < 4; i++)
#pragma unroll
                for (int j = 0; j < 8; j++) mma_bf(acc[i][j], ah[i], bh[j]);

            uint32_t bl[8][2];
#pragma unroll
            for (int p = 0; p < 4; p++) {
                uint32_t t[4];
                ldm4(t, sb + B_BL * 2 + boff + p * 16 * RS * 2 + ko);
                bl[p*2][0] = t[0]; bl[p*2][1] = t[1]; bl[p*2+1][0] = t[2]; bl[p*2+1][1] = t[3];
            }
#pragma unroll
            for (int i = 0; i < 4; i++)
#pragma unroll
                for (int j = 0; j < 8; j++) mma_bf(acc[i][j], ah[i], bl[j]);

            uint32_t al[4][4];
#pragma unroll
            for (int i = 0; i < 4; i++)
                ldm4(al[i], sb + B_AL * 2 + aoff + i * 16 * RS * 2 + ko);
#pragma unroll
            for (int i = 0; i < 4; i++)
#pragma unroll
                for (int j = 0; j < 8; j++) mma_bf(acc[i][j], al[i], bh[j]);
        }
    }

    const int qr = lane >> 2, qc = (lane & 3) * 2;
#pragma unroll
    for (int i = 0; i < 4; i++)
#pragma unroll
        for (int j = 0; j < 8; j++) {
            int cj = wn * 64 + j * 8 + qc;
            acc[i][j][0] += bias_s[cj];     acc[i][j][1] += bias_s[cj + 1];
            acc[i][j][2] += bias_s[cj];     acc[i][j][3] += bias_s[cj + 1];
        }

#pragma unroll
    for (int i = 0; i < 4; i++) {
        float s0 = 0.f, s1 = 0.f;
#pragma unroll
        for (int j = 0; j < 8; j++) {
            s0 += acc[i][j][0] * acc[i][j][0] + acc[i][j][1] * acc[i][j][1];
            s1 += acc[i][j][2] * acc[i][j][2] + acc[i][j][3] * acc[i][j][3];
        }
        s0 += __shfl_xor_sync(0xFFFFFFFFu, s0, 1);
        s0 += __shfl_xor_sync(0xFFFFFFFFu, s0, 2);
        s1 += __shfl_xor_sync(0xFFFFFFFFu, s1, 1);
        s1 += __shfl_xor_sync(0xFFFFFFFFu, s1, 2);
        if ((lane & 3) == 0) {
            int rl = wm * 64 + i * 16 + qr;
            rsq[wn * 128 + rl]     = s0;
            rsq[wn * 128 + rl + 8] = s1;
        }
    }
    __syncthreads();
#pragma unroll
    for (int i = 0; i < 4; i++) {
        int rl = wm * 64 + i * 16 + qr;
        float t0 = rsq[rl]     + rsq[128 + rl]     + rsq[256 + rl]     + rsq[384 + rl];
        float t1 = rsq[rl + 8] + rsq[128 + rl + 8] + rsq[256 + rl + 8] + rsq[384 + rl + 8];
        float sc0 = 16.0f * rsqrtf(t0);
        float sc1 = 16.0f * rsqrtf(t1);
        size_t r0 = (size_t)(m0 + rl);
#pragma unroll
        for (int j = 0; j < 8; j++) {
            int cj = wn * 64 + j * 8 + qc;
            float u00 = acc[i][j][0] * sc0 + nc_s[cj];
            float u01 = acc[i][j][1] * sc0 + nc_s[cj + 1];
            float u10 = acc[i][j][2] * sc1 + nc_s[cj];
            float u11 = acc[i][j][3] * sc1 + nc_s[cj + 1];
            size_t o0 = r0 * N + cj;
            size_t o1 = (r0 + 8) * N + cj;
            *(uint32_t*)(Ch + o0) = pkbf(u00, u01);
            *(uint32_t*)(Ch + o1) = pkbf(u10, u11);
            *(uint32_t*)(Cl + o0) = pkbf(rsd(u00), rsd(u01));
            *(uint32_t*)(Cl + o1) = pkbf(rsd(u10), rsd(u11));
        }
    }
}

// --------------------------------------------------------------------------------
extern "C" void kernel_launch(void* const* d_in, const int* in_sizes, int n_in,
                              void* d_out, int out_size)
{
    const float* x    = (const float*)d_in[0];
    const float* nz   = (const float*)d_in[1];
    const float* W1   = (const float*)d_in[2];
    const float* b1   = (const float*)d_in[3];
    const float* a1   = (const float*)d_in[4];
    const float* gm1  = (const float*)d_in[5];
    const float* bt1  = (const float*)d_in[6];
    const float* W2   = (const float*)d_in[7];
    const float* b2   = (const float*)d_in[8];
    const float* W3   = (const float*)d_in[9];
    const float* b3   = (const float*)d_in[10];
    const float* a2   = (const float*)d_in[11];
    const float* gm2  = (const float*)d_in[12];
    const float* bt2  = (const float*)d_in[13];
    const float* W4   = (const float*)d_in[14];
    const float* b4   = (const float*)d_in[15];
    const float* fir  = (const float*)d_in[16];
    float* out = (float*)d_out;

    __nv_bfloat16 *xh, *xl, *h1h, *h1l, *ych, *ycl, *ddh, *ddl;
    __nv_bfloat16 *W1h, *W1l, *W2h, *W2l, *W3h, *W3l, *W4h, *W4l;
    float *b2f, *b4f, *st, *part, *nc;
    cudaGetSymbolAddress((void**)&xh,  g_xh);   cudaGetSymbolAddress((void**)&xl,  g_xl);
    cudaGetSymbolAddress((void**)&h1h, g_h1h);  cudaGetSymbolAddress((void**)&h1l, g_h1l);
    cudaGetSymbolAddress((void**)&ych, g_ych);  cudaGetSymbolAddress((void**)&ycl, g_ycl);
    cudaGetSymbolAddress((void**)&ddh, g_ddh);  cudaGetSymbolAddress((void**)&ddl, g_ddl);
    cudaGetSymbolAddress((void**)&W1h, g_W1h);  cudaGetSymbolAddress((void**)&W1l, g_W1l);
    cudaGetSymbolAddress((void**)&W2h, g_W2h);  cudaGetSymbolAddress((void**)&W2l, g_W2l);
    cudaGetSymbolAddress((void**)&W3h, g_W3h);  cudaGetSymbolAddress((void**)&W3l, g_W3l);
    cudaGetSymbolAddress((void**)&W4h, g_W4h);  cudaGetSymbolAddress((void**)&W4l, g_W4l);
    cudaGetSymbolAddress((void**)&b2f, g_b2f);
    cudaGetSymbolAddress((void**)&b4f, g_b4f);
    cudaGetSymbolAddress((void**)&st,  g_stats);
    cudaGetSymbolAddress((void**)&part,g_part);
    cudaGetSymbolAddress((void**)&nc,  g_nc);

    const int SMEM_A = A_HDR + STAGES * A_STAGE_B;   // 192512
    const int SMEM_B = B_HDR + STAGES * B_STAGE_B;   // 188416
    cudaFuncSetAttribute(gemm_a<0, false>, cudaFuncAttributeMaxDynamicSharedMemorySize, SMEM_A);
    cudaFuncSetAttribute(gemm_a<1, true>,  cudaFuncAttributeMaxDynamicSharedMemorySize, SMEM_A);
    cudaFuncSetAttribute(gemm_b,           cudaFuncAttributeMaxDynamicSharedMemorySize, SMEM_B);

    // 0) fused prep (x split + W1/W3 splits + FIR noise)
    prep_kernel<<<SPLITX_BLOCKS + W1_BLOCKS + W3_BLOCKS + 1, 256>>>(
        x, xh, xl, W1, W1h, W1l, W3, W3h, W3l, nz, fir, nc,
        out + (size_t)B_ROWS * BLK);

    // 1) h1 = prelu(x @ W1^T + b1) -> bf16 hi/lo, fused BN1 column partials
    gemm_a<1, true><<<dim3(BLK / A_CN, B_ROWS / A_CM), 512, SMEM_A>>>(
        xh, xl, W1h, W1l, b1, nullptr, h1h, h1l, B_ROWS, BLK, BLK, a1, part);

    // 2) BN1 reduce + fold into W2
    stats_reduce2<<<BLK, 256>>>(part, st, st + BLK, BLK);
    fold_kernel<<<CUN, 128>>>(W2, b2, gm1, bt1, st, st + BLK, W2h, W2l, b2f, BLK);

    // 3) yc = 16*(h1_bn @ W2^T + b2)/||row|| + noise -> bf16 hi/lo
    gemm_b<<<dim3(1, B_ROWS / 128), 256, SMEM_B>>>(
        h1h, h1l, W2h, W2l, b2f, ych, ycl, B_ROWS, CUN, BLK, nc);

    // 4) d = prelu(yc @ W3^T + b3) -> bf16 hi/lo, fused BN2 column partials
    gemm_a<1, true><<<dim3(BLK / A_CN, B_ROWS / A_CM), 512, SMEM_A>>>(
        ych, ycl, W3h, W3l, b3, nullptr, ddh, ddl, B_ROWS, BLK, CUN, a2, part);

    // 5) BN2 reduce + fold into W4
    stats_reduce2<<<BLK, 256>>>(part, st + 2 * BLK, st + 3 * BLK, BLK);
    fold_kernel<<<BLK, 128>>>(W4, b4, gm2, bt2, st + 2 * BLK, st + 3 * BLK, W4h, W4l, b4f, BLK);

    // 6) out = d_bn @ W4^T + b4 (fp32)
    gemm_a<0, false><<<dim3(BLK / A_CN, B_ROWS / A_CM), 512, SMEM_A>>>(
        ddh, ddl, W4h, W4l, b4f, out, nullptr, nullptr, B_ROWS, BLK, BLK, nullptr, nullptr);

    (void)in_sizes; (void)n_in; (void)out_size;
}

// round 10
// speedup vs baseline: 3.2709x; 1.4115x over previous
#include <cuda_runtime.h>
#include <cuda_fp16.h>
#include <math.h>
#include <stdint.h>

#define B_ROWS 65536
#define BLK    512
#define CUN    256
#define TAPSN  100

#define KTT    32
#define RS     40                         // padded SMEM row stride (elems) -> 80 B

// ---- shape A (G1/G3/G4): CTA 256x128, 512 thr, warp 64x32, A single fp16 ----
#define A_ST   5
#define A_A    0
#define A_BH   (256 * RS)
#define A_BL   (384 * RS)
#define A_STAGE_B (512 * RS * 2)          // 40960
#define A_HDR  8192

// ---- shape B (G2 rownorm): CTA 128x256, 256 thr, warp 64x64 ----
#define B_ST   4
#define B_A    0
#define B_BH   (128 * RS)
#define B_BL   (384 * RS)
#define B_STAGE_B (640 * RS * 2)          // 51200
#define B_HDR  4096

// ---------------- device scratch ----------------
static __device__ __half g_x16[(size_t)B_ROWS * BLK];
static __device__ __half g_h1 [(size_t)B_ROWS * BLK];
static __device__ __half g_yc [(size_t)B_ROWS * CUN];
static __device__ __half g_dd [(size_t)B_ROWS * BLK];
static __device__ __half g_W1h[BLK * BLK], g_W1l[BLK * BLK];
static __device__ __half g_W2h[CUN * BLK], g_W2l[CUN * BLK];
static __device__ __half g_W3h[BLK * CUN], g_W3l[BLK * CUN];
static __device__ __half g_W4h[BLK * BLK], g_W4l[BLK * BLK];
static __device__ float g_b2f[CUN], g_b4f[BLK];
static __device__ float g_stats[4 * BLK];
static __device__ float g_part [256 * 2 * BLK];   // [mblock][2][512]
static __device__ float g_nc  [CUN];

// ---------------- helpers ----------------
__device__ __forceinline__ uint32_t s2u(const void* p) {
    return (uint32_t)__cvta_generic_to_shared(p);
}
__device__ __forceinline__ void cpa16(uint32_t d, const void* s) {
    asm volatile("cp.async.cg.shared.global [%0], [%1], 16;" :: "r"(d), "l"(s));
}
__device__ __forceinline__ void ldm4(uint32_t* f, uint32_t a) {
    asm volatile("ldmatrix.sync.aligned.m8n8.x4.shared.b16 {%0,%1,%2,%3}, [%4];"
                 : "=r"(f[0]), "=r"(f[1]), "=r"(f[2]), "=r"(f[3]) : "r"(a));
}
__device__ __forceinline__ void mma_h(float* d, const uint32_t* a, const uint32_t* b) {
    asm volatile("mma.sync.aligned.m16n8k16.row.col.f32.f16.f16.f32 "
                 "{%0,%1,%2,%3}, {%4,%5,%6,%7}, {%8,%9}, {%0,%1,%2,%3};"
                 : "+f"(d[0]), "+f"(d[1]), "+f"(d[2]), "+f"(d[3])
                 : "r"(a[0]), "r"(a[1]), "r"(a[2]), "r"(a[3]), "r"(b[0]), "r"(b[1]));
}
__device__ __forceinline__ uint32_t pkh(float a, float b) {
    __half2 h = __floats2half2_rn(a, b);
    return *(uint32_t*)&h;
}

// ---------------- fused prep: x->fp16 | W1 split | W3 split | FIR noise ---------
#define SPLITX_BLOCKS 32768
#define W1_BLOCKS     1024
#define W3_BLOCKS     512
__global__ void prep_kernel(const float* __restrict__ x, __half* __restrict__ x16,
                            const float* __restrict__ W1,
                            __half* __restrict__ W1h, __half* __restrict__ W1l,
                            const float* __restrict__ W3,
                            __half* __restrict__ W3h, __half* __restrict__ W3l,
                            const float* __restrict__ noise, const float* __restrict__ fir,
                            float* __restrict__ nc, float* __restrict__ out_tail)
{
    int bid = blockIdx.x, tid = threadIdx.x;
    if (bid < SPLITX_BLOCKS) {
        int i = bid * 256 + tid;
        float4 v = ((const float4*)x)[i];
        ((uint2*)x16)[i] = make_uint2(pkh(v.x, v.y), pkh(v.z, v.w));
    } else if (bid < SPLITX_BLOCKS + W1_BLOCKS) {
        int i = (bid - SPLITX_BLOCKS) * 256 + tid;
        float v = W1[i];
        __half h = __float2half_rn(v);
        W1h[i] = h;
        W1l[i] = __float2half_rn(v - __half2float(h));
    } else if (bid < SPLITX_BLOCKS + W1_BLOCKS + W3_BLOCKS) {
        int i = (bid - SPLITX_BLOCKS - W1_BLOCKS) * 256 + tid;
        float v = W3[i];
        __half h = __float2half_rn(v);
        W3h[i] = h;
        W3l[i] = __float2half_rn(v - __half2float(h));
    } else {
        int i = tid;
        double snr_lin = pow(10.0, 0.7);
        float nstd = (float)sqrt(1.0 / (2.0 * 2.0 * snr_lin));   // rate = 2
        float acc = 0.f;
#pragma unroll 4
        for (int t = 0; t < TAPSN; t++) {
            int idx = i + 49 - t;
            if (idx >= 0 && idx < CUN) acc += fir[t] * (noise[idx] * nstd);
        }
        nc[i] = acc;
        out_tail[i] = acc;
    }
}

__global__ void stats_reduce2(const float* __restrict__ part,
                              float* __restrict__ sum, float* __restrict__ sq, int Ncols)
{
    int c = blockIdx.x;
    int t = threadIdx.x;
    float s = part[((size_t)t * 2    ) * Ncols + c];
    float q = part[((size_t)t * 2 + 1) * Ncols + c];
#pragma unroll
    for (int o = 16; o > 0; o >>= 1) {
        s += __shfl_down_sync(0xFFFFFFFFu, s, o);
        q += __shfl_down_sync(0xFFFFFFFFu, q, o);
    }
    __shared__ float sh[64];
    int w = t >> 5, l = t & 31;
    if (l == 0) { sh[w] = s; sh[32 + w] = q; }
    __syncthreads();
    if (t == 0) {
        float S = 0.f, Q = 0.f;
        for (int i = 0; i < 8; i++) { S += sh[i]; Q += sh[32 + i]; }
        sum[c] = S; sq[c] = Q;
    }
}

__global__ void fold_kernel(const float* __restrict__ Wsrc, const float* __restrict__ bsrc,
                            const float* __restrict__ gam,  const float* __restrict__ bt,
                            const float* __restrict__ sum,  const float* __restrict__ sq,
                            __half* __restrict__ Whi, __half* __restrict__ Wlo,
                            float* __restrict__ bdst, int Kin)
{
    int j = blockIdx.x;
    int tid = threadIdx.x;  // 128
    const float invB = 1.0f / (float)B_ROWS;
    float partial = 0.f;
    for (int k = tid; k < Kin; k += 128) {
        float mu  = sum[k] * invB;
        float var = sq[k] * invB - mu * mu;
        float rs  = rsqrtf(var + 1e-5f);
        float s   = gam[k] * rs;
        float w   = Wsrc[(size_t)j * Kin + k];
        float wf  = w * s;
        __half h = __float2half_rn(wf);
        Whi[(size_t)j * Kin + k] = h;
        Wlo[(size_t)j * Kin + k] = __float2half_rn(wf - __half2float(h));
        partial += w * (bt[k] - mu * s);
    }
    __shared__ float sh[128];
    sh[tid] = partial; __syncthreads();
    for (int s = 64; s > 0; s >>= 1) { if (tid < s) sh[tid] += sh[tid + s]; __syncthreads(); }
    if (tid == 0) bdst[j] = bsrc[j] + sh[0];
}

// ================= shape A: CTA 256x128, 512 thr, 16 warps (4x4), warp 64x32 =====
// C = epi(A @ (Wh+Wl)^T + bias); A single fp16. 2 MMA terms per k16.
// EPI: 0 -> fp32 out; 1 -> PReLU -> fp16 out. STATS: per-CTA column partials.
template <int EPI, bool STATS>
__global__ void __launch_bounds__(512, 1)
gemm_a(const __half* __restrict__ Ax,
       const __half* __restrict__ BH, const __half* __restrict__ BL,
       const float* __restrict__ bias,
       float* __restrict__ Cf, __half* __restrict__ Ch,
       int M, int N, int K, const float* __restrict__ alpha_ptr,
       float* __restrict__ part)
{
    extern __shared__ char smem[];
    float* bias_s = (float*)smem;                 // 128 f
    float* s_sm   = (float*)(smem + 1024);        // 4 x 128
    float* q_sm   = (float*)(smem + 3072);        // 4 x 128
    char*  stage0 = smem + A_HDR;

    const int tid = threadIdx.x;
    const int lane = tid & 31, wid = tid >> 5;
    const int wm = wid & 3, wn = wid >> 2;        // 4 x 4 warps, tile 64 x 32
    const int m0 = blockIdx.y * 256, n0 = blockIdx.x * 128;

    if (tid < 128) bias_s[tid] = bias[n0 + tid];

    float acc[4][4][4];
#pragma unroll
    for (int i = 0; i < 4; i++)
#pragma unroll
        for (int j = 0; j < 4; j++)
#pragma unroll
            for (int r = 0; r < 4; r++) acc[i][j][r] = 0.f;

    const int nit = K / KTT;

    auto load_stage = [&](int s, int k0) {
        uint32_t sb = s2u(stage0 + s * A_STAGE_B);
#pragma unroll
        for (int i = 0; i < 4; i++) {
            int ch = tid + i * 512;               // 0..2047
            uint32_t dst; const __half* g;
            if (ch < 1024) {                      // A: 256 rows x 4 chunks
                int r = ch >> 2, c = ch & 3;
                dst = sb + (A_A + r * RS) * 2 + c * 16;
                g = Ax + (size_t)(m0 + r) * K + k0 + c * 8;
            } else if (ch < 1536) {               // BH: 128 rows x 4
                int l = ch - 1024; int r = l >> 2, c = l & 3;
                dst = sb + (A_BH + r * RS) * 2 + c * 16;
                g = BH + (size_t)(n0 + r) * K + k0 + c * 8;
            } else {                              // BL
                int l = ch - 1536; int r = l >> 2, c = l & 3;
                dst = sb + (A_BL + r * RS) * 2 + c * 16;
                g = BL + (size_t)(n0 + r) * K + k0 + c * 8;
            }
            cpa16(dst, g);
        }
    };

    for (int s = 0; s < A_ST - 1; s++) {
        if (s < nit) load_stage(s, s * KTT);
        asm volatile("cp.async.commit_group;" ::: "memory");
    }

    const uint32_t aoff = (uint32_t)(((wm * 64 + (lane & 15)) * RS + (lane >> 4) * 8) * 2);
    const uint32_t boff = (uint32_t)(((wn * 32 + (lane & 7) + ((lane >> 4) << 3)) * RS
                                      + ((lane >> 3) & 1) * 8) * 2);

    for (int it = 0; it < nit; it++) {
        asm volatile("cp.async.wait_group %0;" :: "n"(A_ST - 2) : "memory");
        __syncthreads();
        int ns = it + A_ST - 1;
        if (ns < nit) load_stage(ns % A_ST, ns * KTT);
        asm volatile("cp.async.commit_group;" ::: "memory");

        uint32_t sb = s2u(stage0 + (it % A_ST) * A_STAGE_B);
#pragma unroll
        for (int k16 = 0; k16 < 2; k16++) {
            uint32_t ko = k16 * 32;
            uint32_t ah[4][4], b0[4][2];
#pragma unroll
            for (int i = 0; i < 4; i++)
                ldm4(ah[i], sb + A_A * 2 + aoff + i * 16 * RS * 2 + ko);
#pragma unroll
            for (int p = 0; p < 2; p++) {
                uint32_t t[4];
                ldm4(t, sb + A_BH * 2 + boff + p * 16 * RS * 2 + ko);
                b0[p*2][0] = t[0]; b0[p*2][1] = t[1]; b0[p*2+1][0] = t[2]; b0[p*2+1][1] = t[3];
            }
#pragma unroll
            for (int i = 0; i < 4; i++)
#pragma unroll
                for (int j = 0; j < 4; j++) mma_h(acc[i][j], ah[i], b0[j]);

            uint32_t b1[4][2];
#pragma unroll
            for (int p = 0; p < 2; p++) {
                uint32_t t[4];
                ldm4(t, sb + A_BL * 2 + boff + p * 16 * RS * 2 + ko);
                b1[p*2][0] = t[0]; b1[p*2][1] = t[1]; b1[p*2+1][0] = t[2]; b1[p*2+1][1] = t[3];
            }
#pragma unroll
            for (int i = 0; i < 4; i++)
#pragma unroll
                for (int j = 0; j < 4; j++) mma_h(acc[i][j], ah[i], b1[j]);
        }
    }

    // -------- epilogue --------
    const int qr = lane >> 2, qc = (lane & 3) * 2;
    float alpha = (EPI == 1) ? *alpha_ptr : 0.f;
    float cs0[4], cs1[4], cq0[4], cq1[4];
    if (STATS)
#pragma unroll
        for (int j = 0; j < 4; j++) { cs0[j] = cs1[j] = cq0[j] = cq1[j] = 0.f; }

#pragma unroll
    for (int i = 0; i < 4; i++) {
        int rl = wm * 64 + i * 16 + qr;
        size_t r0 = (size_t)(m0 + rl);
#pragma unroll
        for (int j = 0; j < 4; j++) {
            int cj = wn * 32 + j * 8 + qc;
            float b0 = bias_s[cj], b1 = bias_s[cj + 1];
            float v00 = acc[i][j][0] + b0, v01 = acc[i][j][1] + b1;
            float v10 = acc[i][j][2] + b0, v11 = acc[i][j][3] + b1;
            if (EPI == 1) {
                v00 = v00 > 0.f ? v00 : alpha * v00;
                v01 = v01 > 0.f ? v01 : alpha * v01;
                v10 = v10 > 0.f ? v10 : alpha * v10;
                v11 = v11 > 0.f ? v11 : alpha * v11;
            }
            if (STATS) {
                cs0[j] += v00 + v10;  cq0[j] += v00 * v00 + v10 * v10;
                cs1[j] += v01 + v11;  cq1[j] += v01 * v01 + v11 * v11;
            }
            size_t o0 = r0 * N + n0 + cj;
            size_t o1 = (r0 + 8) * N + n0 + cj;
            if (EPI == 0) {
                *(float2*)(Cf + o0) = make_float2(v00, v01);
                *(float2*)(Cf + o1) = make_float2(v10, v11);
            } else {
                *(uint32_t*)(Ch + o0) = pkh(v00, v01);
                *(uint32_t*)(Ch + o1) = pkh(v10, v11);
            }
        }
    }

    if (STATS) {
#pragma unroll
        for (int j = 0; j < 4; j++) {
#pragma unroll
            for (int o = 4; o <= 16; o <<= 1) {
                cs0[j] += __shfl_xor_sync(0xFFFFFFFFu, cs0[j], o);
                cs1[j] += __shfl_xor_sync(0xFFFFFFFFu, cs1[j], o);
                cq0[j] += __shfl_xor_sync(0xFFFFFFFFu, cq0[j], o);
                cq1[j] += __shfl_xor_sync(0xFFFFFFFFu, cq1[j], o);
            }
        }
        if (lane < 4) {
#pragma unroll
            for (int j = 0; j < 4; j++) {
                int cj = wn * 32 + j * 8 + lane * 2;
                s_sm[wm * 128 + cj]     = cs0[j];
                s_sm[wm * 128 + cj + 1] = cs1[j];
                q_sm[wm * 128 + cj]     = cq0[j];
                q_sm[wm * 128 + cj + 1] = cq1[j];
            }
        }
        __syncthreads();
        if (tid < 128) {
            float S = s_sm[tid] + s_sm[128 + tid] + s_sm[256 + tid] + s_sm[384 + tid];
            float Q = q_sm[tid] + q_sm[128 + tid] + q_sm[256 + tid] + q_sm[384 + tid];
            part[((size_t)blockIdx.y * 2    ) * N + n0 + tid] = S;
            part[((size_t)blockIdx.y * 2 + 1) * N + n0 + tid] = Q;
        }
    }
}

// ================= shape B (G2): CTA 128x256, 256 thr, rownorm+noise epilogue ====
__global__ void __launch_bounds__(256, 1)
gemm_b(const __half* __restrict__ Ax,
       const __half* __restrict__ BH, const __half* __restrict__ BL,
       const float* __restrict__ bias, __half* __restrict__ Ch,
       int M, int N, int K, const float* __restrict__ nc)
{
    extern __shared__ char smem[];
    float* bias_s = (float*)smem;
    float* nc_s   = (float*)(smem + 1024);
    float* rsq    = (float*)(smem + 2048);
    char*  stage0 = smem + B_HDR;

    const int tid = threadIdx.x;
    const int lane = tid & 31, wid = tid >> 5;
    const int wm = wid & 1, wn = wid >> 1;
    const int m0 = blockIdx.y * 128;

    bias_s[tid] = bias[tid];
    nc_s[tid] = nc[tid];

    float acc[4][8][4];
#pragma unroll
    for (int i = 0; i < 4; i++)
#pragma unroll
        for (int j = 0; j < 8; j++)
#pragma unroll
            for (int r = 0; r < 4; r++) acc[i][j][r] = 0.f;

    const int nit = K / KTT;

    auto load_stage = [&](int s, int k0) {
        uint32_t sb = s2u(stage0 + s * B_STAGE_B);
#pragma unroll
        for (int i = 0; i < 10; i++) {
            int ch = tid + i * 256;               // 0..2559
            uint32_t dst; const __half* g;
            if (ch < 512) {                       // A: 128 rows x 4
                int r = ch >> 2, c = ch & 3;
                dst = sb + (B_A + r * RS) * 2 + c * 16;
                g = Ax + (size_t)(m0 + r) * K + k0 + c * 8;
            } else if (ch < 1536) {               // BH: 256 rows x 4
                int l = ch - 512; int r = l >> 2, c = l & 3;
                dst = sb + (B_BH + r * RS) * 2 + c * 16;
                g = BH + (size_t)r * K + k0 + c * 8;
            } else {                              // BL
                int l = ch - 1536; int r = l >> 2, c = l & 3;
                dst = sb + (B_BL + r * RS) * 2 + c * 16;
                g = BL + (size_t)r * K + k0 + c * 8;
            }
            cpa16(dst, g);
        }
    };

    for (int s = 0; s < B_ST - 1; s++) {
        if (s < nit) load_stage(s, s * KTT);
        asm volatile("cp.async.commit_group;" ::: "memory");
    }

    const uint32_t aoff = (uint32_t)(((wm * 64 + (lane & 15)) * RS + (lane >> 4) * 8) * 2);
    const uint32_t boff = (uint32_t)(((wn * 64 + (lane & 7) + ((lane >> 4) << 3)) * RS
                                      + ((lane >> 3) & 1) * 8) * 2);

    for (int it = 0; it < nit; it++) {
        asm volatile("cp.async.wait_group %0;" :: "n"(B_ST - 2) : "memory");
        __syncthreads();
        int ns = it + B_ST - 1;
        if (ns < nit) load_stage(ns % B_ST, ns * KTT);
        asm volatile("cp.async.commit_group;" ::: "memory");

        uint32_t sb = s2u(stage0 + (it % B_ST) * B_STAGE_B);
#pragma unroll
        for (int k16 = 0; k16 < 2; k16++) {
            uint32_t ko = k16 * 32;
            uint32_t ah[4][4], bh[8][2];
#pragma unroll
            for (int i = 0; i < 4; i++)
                ldm4(ah[i], sb + B_A * 2 + aoff + i * 16 * RS * 2 + ko);
#pragma unroll
            for (int p = 0; p < 4; p++) {
                uint32_t t[4];
                ldm4(t, sb + B_BH * 2 + boff + p * 16 * RS * 2 + ko);
                bh[p*2][0] = t[0]; bh[p*2][1] = t[1]; bh[p*2+1][0] = t[2]; bh[p*2+1][1] = t[3];
            }
#pragma unroll
            for (int i = 0; i < 4; i++)
#pragma unroll
                for (int j = 0; j < 8; j++) mma_h(acc[i][j], ah[i], bh[j]);

            uint32_t bl[8][2];
#pragma unroll
            for (int p = 0; p < 4; p++) {
                uint32_t t[4];
                ldm4(t, sb + B_BL * 2 + boff + p * 16 * RS * 2 + ko);
                bl[p*2][0] = t[0]; bl[p*2][1] = t[1]; bl[p*2+1][0] = t[2]; bl[p*2+1][1] = t[3];
            }
#pragma unroll
            for (int i = 0; i < 4; i++)
#pragma unroll
                for (int j = 0; j < 8; j++) mma_h(acc[i][j], ah[i], bl[j]);
        }
    }

    const int qr = lane >> 2, qc = (lane & 3) * 2;
#pragma unroll
    for (int i = 0; i < 4; i++)
#pragma unroll
        for (int j = 0; j < 8; j++) {
            int cj = wn * 64 + j * 8 + qc;
            acc[i][j][0] += bias_s[cj];     acc[i][j][1] += bias_s[cj + 1];
            acc[i][j][2] += bias_s[cj];     acc[i][j][3] += bias_s[cj + 1];
        }

#pragma unroll
    for (int i = 0; i < 4; i++) {
        float s0 = 0.f, s1 = 0.f;
#pragma unroll
        for (int j = 0; j < 8; j++) {
            s0 += acc[i][j][0] * acc[i][j][0] + acc[i][j][1] * acc[i][j][1];
            s1 += acc[i][j][2] * acc[i][j][2] + acc[i][j][3] * acc[i][j][3];
        }
        s0 += __shfl_xor_sync(0xFFFFFFFFu, s0, 1);
        s0 += __shfl_xor_sync(0xFFFFFFFFu, s0, 2);
        s1 += __shfl_xor_sync(0xFFFFFFFFu, s1, 1);
        s1 += __shfl_xor_sync(0xFFFFFFFFu, s1, 2);
        if ((lane & 3) == 0) {
            int rl = wm * 64 + i * 16 + qr;
            rsq[wn * 128 + rl]     = s0;
            rsq[wn * 128 + rl + 8] = s1;
        }
    }
    __syncthreads();
#pragma unroll
    for (int i = 0; i < 4; i++) {
        int rl = wm * 64 + i * 16 + qr;
        float t0 = rsq[rl]     + rsq[128 + rl]     + rsq[256 + rl]     + rsq[384 + rl];
        float t1 = rsq[rl + 8] + rsq[128 + rl + 8] + rsq[256 + rl + 8] + rsq[384 + rl + 8];
        float sc0 = 16.0f * rsqrtf(t0);   // sqrt(CU) = 16
        float sc1 = 16.0f * rsqrtf(t1);
        size_t r0 = (size_t)(m0 + rl);
#pragma unroll
        for (int j = 0; j < 8; j++) {
            int cj = wn * 64 + j * 8 + qc;
            float u00 = acc[i][j][0] * sc0 + nc_s[cj];
            float u01 = acc[i][j][1] * sc0 + nc_s[cj + 1];
            float u10 = acc[i][j][2] * sc1 + nc_s[cj];
            float u11 = acc[i][j][3] * sc1 + nc_s[cj + 1];
            size_t o0 = r0 * N + cj;
            size_t o1 = (r0 + 8) * N + cj;
            *(uint32_t*)(Ch + o0) = pkh(u00, u01);
            *(uint32_t*)(Ch + o1) = pkh(u10, u11);
        }
    }
}

// --------------------------------------------------------------------------------
extern "C" void kernel_launch(void* const* d_in, const int* in_sizes, int n_in,
                              void* d_out, int out_size)
{
    const float* x    = (const float*)d_in[0];
    const float* nz   = (const float*)d_in[1];
    const float* W1   = (const float*)d_in[2];
    const float* b1   = (const float*)d_in[3];
    const float* a1   = (const float*)d_in[4];
    const float* gm1  = (const float*)d_in[5];
    const float* bt1  = (const float*)d_in[6];
    const float* W2   = (const float*)d_in[7];
    const float* b2   = (const float*)d_in[8];
    const float* W3   = (const float*)d_in[9];
    const float* b3   = (const float*)d_in[10];
    const float* a2   = (const float*)d_in[11];
    const float* gm2  = (const float*)d_in[12];
    const float* bt2  = (const float*)d_in[13];
    const float* W4   = (const float*)d_in[14];
    const float* b4   = (const float*)d_in[15];
    const float* fir  = (const float*)d_in[16];
    float* out = (float*)d_out;

    __half *x16, *h1, *yc, *dd;
    __half *W1h, *W1l, *W2h, *W2l, *W3h, *W3l, *W4h, *W4l;
    float *b2f, *b4f, *st, *part, *nc;
    cudaGetSymbolAddress((void**)&x16, g_x16);
    cudaGetSymbolAddress((void**)&h1,  g_h1);
    cudaGetSymbolAddress((void**)&yc,  g_yc);
    cudaGetSymbolAddress((void**)&dd,  g_dd);
    cudaGetSymbolAddress((void**)&W1h, g_W1h);  cudaGetSymbolAddress((void**)&W1l, g_W1l);
    cudaGetSymbolAddress((void**)&W2h, g_W2h);  cudaGetSymbolAddress((void**)&W2l, g_W2l);
    cudaGetSymbolAddress((void**)&W3h, g_W3h);  cudaGetSymbolAddress((void**)&W3l, g_W3l);
    cudaGetSymbolAddress((void**)&W4h, g_W4h);  cudaGetSymbolAddress((void**)&W4l, g_W4l);
    cudaGetSymbolAddress((void**)&b2f, g_b2f);
    cudaGetSymbolAddress((void**)&b4f, g_b4f);
    cudaGetSymbolAddress((void**)&st,  g_stats);
    cudaGetSymbolAddress((void**)&part,g_part);
    cudaGetSymbolAddress((void**)&nc,  g_nc);

    const int SMEM_A = A_HDR + A_ST * A_STAGE_B;   // 8192 + 204800 = 212992
    const int SMEM_B = B_HDR + B_ST * B_STAGE_B;   // 4096 + 204800 = 208896
    cudaFuncSetAttribute(gemm_a<0, false>, cudaFuncAttributeMaxDynamicSharedMemorySize, SMEM_A);
    cudaFuncSetAttribute(gemm_a<1, true>,  cudaFuncAttributeMaxDynamicSharedMemorySize, SMEM_A);
    cudaFuncSetAttribute(gemm_b,           cudaFuncAttributeMaxDynamicSharedMemorySize, SMEM_B);

    // 0) fused prep (x -> fp16, W1/W3 fp16 hi/lo splits, FIR noise)
    prep_kernel<<<SPLITX_BLOCKS + W1_BLOCKS + W3_BLOCKS + 1, 256>>>(
        x, x16, W1, W1h, W1l, W3, W3h, W3l, nz, fir, nc,
        out + (size_t)B_ROWS * BLK);

    // 1) h1 = prelu(x @ W1^T + b1) -> fp16, fused BN1 column partials
    gemm_a<1, true><<<dim3(BLK / 128, B_ROWS / 256), 512, SMEM_A>>>(
        x16, W1h, W1l, b1, nullptr, h1, B_ROWS, BLK, BLK, a1, part);

    // 2) BN1 reduce + fold into W2 (fp16 hi/lo)
    stats_reduce2<<<BLK, 256>>>(part, st, st + BLK, BLK);
    fold_kernel<<<CUN, 128>>>(W2, b2, gm1, bt1, st, st + BLK, W2h, W2l, b2f, BLK);

    // 3) yc = 16*(h1_bn @ W2^T + b2)/||row|| + noise -> fp16
    gemm_b<<<dim3(1, B_ROWS / 128), 256, SMEM_B>>>(
        h1, W2h, W2l, b2f, yc, B_ROWS, CUN, BLK, nc);

    // 4) d = prelu(yc @ W3^T + b3) -> fp16, fused BN2 column partials
    gemm_a<1, true><<<dim3(BLK / 128, B_ROWS / 256), 512, SMEM_A>>>(
        yc, W3h, W3l, b3, nullptr, dd, B_ROWS, BLK, CUN, a2, part);

    // 5) BN2 reduce + fold into W4
    stats_reduce2<<<BLK, 256>>>(part, st + 2 * BLK, st + 3 * BLK, BLK);
    fold_kernel<<<BLK, 128>>>(W4, b4, gm2, bt2, st + 2 * BLK, st + 3 * BLK, W4h, W4l, b4f, BLK);

    // 6) out = d_bn @ W4^T + b4 (fp32)
    gemm_a<0, false><<<dim3(BLK / 128, B_ROWS / 256), 512, SMEM_A>>>(
        dd, W4h, W4l, b4f, out, nullptr, B_ROWS, BLK, BLK, nullptr, nullptr);

    (void)in_sizes; (void)n_in; (void)out_size;
}

// round 14
// speedup vs baseline: 4.1006x; 1.2536x over previous
#include <cuda_runtime.h>
#include <cuda_fp16.h>
#include <math.h>
#include <stdint.h>

#define B_ROWS 65536
#define BLK    512
#define CUN    256
#define TAPSN  100

#define KTT    32
#define RS     40                         // padded SMEM row stride (elems) -> 80 B

// ---- shape A (G1/G3/G4): CTA 256x128, 512 thr, warp 64x32, A single fp16 ----
#define A_ST   5
#define A_A    0
#define A_BH   (256 * RS)
#define A_BL   (384 * RS)
#define A_STAGE_B (512 * RS * 2)          // 40960
#define A_HDR  8192

// ---- shape B (G2 rownorm): CTA 128x256, 256 thr, warp 64x64 ----
#define B_ST   4
#define B_A    0
#define B_BH   (128 * RS)
#define B_BL   (384 * RS)
#define B_STAGE_B (640 * RS * 2)          // 51200
#define B_HDR  4096

// ---------------- device scratch ----------------
static __device__ __half g_x16[(size_t)B_ROWS * BLK];
static __device__ __half g_h1 [(size_t)B_ROWS * BLK];
static __device__ __half g_yc [(size_t)B_ROWS * CUN];
static __device__ __half g_dd [(size_t)B_ROWS * BLK];
static __device__ __half g_W1h[BLK * BLK], g_W1l[BLK * BLK];
static __device__ __half g_W2h[CUN * BLK], g_W2l[CUN * BLK];
static __device__ __half g_W3h[BLK * CUN], g_W3l[BLK * CUN];
static __device__ __half g_W4h[BLK * BLK], g_W4l[BLK * BLK];
static __device__ float g_b2f[CUN], g_b4f[BLK];
static __device__ float g_stats[4 * BLK];
static __device__ float g_part [256 * 2 * BLK];   // [mblock][2][512]
static __device__ float g_nc  [CUN];

// ---------------- helpers ----------------
__device__ __forceinline__ uint32_t s2u(const void* p) {
    return (uint32_t)__cvta_generic_to_shared(p);
}
__device__ __forceinline__ void cpa16(uint32_t d, const void* s) {
    asm volatile("cp.async.cg.shared.global [%0], [%1], 16;" :: "r"(d), "l"(s));
}
__device__ __forceinline__ void ldm4(uint32_t* f, uint32_t a) {
    asm volatile("ldmatrix.sync.aligned.m8n8.x4.shared.b16 {%0,%1,%2,%3}, [%4];"
                 : "=r"(f[0]), "=r"(f[1]), "=r"(f[2]), "=r"(f[3]) : "r"(a));
}
__device__ __forceinline__ void mma_h(float* d, const uint32_t* a, const uint32_t* b) {
    asm volatile("mma.sync.aligned.m16n8k16.row.col.f32.f16.f16.f32 "
                 "{%0,%1,%2,%3}, {%4,%5,%6,%7}, {%8,%9}, {%0,%1,%2,%3};"
                 : "+f"(d[0]), "+f"(d[1]), "+f"(d[2]), "+f"(d[3])
                 : "r"(a[0]), "r"(a[1]), "r"(a[2]), "r"(a[3]), "r"(b[0]), "r"(b[1]));
}
__device__ __forceinline__ uint32_t pkh(float a, float b) {
    __half2 h = __floats2half2_rn(a, b);
    return *(uint32_t*)&h;
}

// ---------------- fused prep: x->fp16 | W1 split | W3 split | FIR noise ---------
#define SPLITX_BLOCKS 32768
#define W1_BLOCKS     1024
#define W3_BLOCKS     512
__global__ void prep_kernel(const float* __restrict__ x, __half* __restrict__ x16,
                            const float* __restrict__ W1,
                            __half* __restrict__ W1h, __half* __restrict__ W1l,
                            const float* __restrict__ W3,
                            __half* __restrict__ W3h, __half* __restrict__ W3l,
                            const float* __restrict__ noise, const float* __restrict__ fir,
                            float* __restrict__ nc, float* __restrict__ out_tail)
{
    int bid = blockIdx.x, tid = threadIdx.x;
    if (bid < SPLITX_BLOCKS) {
        int i = bid * 256 + tid;
        float4 v = ((const float4*)x)[i];
        ((uint2*)x16)[i] = make_uint2(pkh(v.x, v.y), pkh(v.z, v.w));
    } else if (bid < SPLITX_BLOCKS + W1_BLOCKS) {
        int i = (bid - SPLITX_BLOCKS) * 256 + tid;
        float v = W1[i];
        __half h = __float2half_rn(v);
        W1h[i] = h;
        W1l[i] = __float2half_rn(v - __half2float(h));
    } else if (bid < SPLITX_BLOCKS + W1_BLOCKS + W3_BLOCKS) {
        int i = (bid - SPLITX_BLOCKS - W1_BLOCKS) * 256 + tid;
        float v = W3[i];
        __half h = __float2half_rn(v);
        W3h[i] = h;
        W3l[i] = __float2half_rn(v - __half2float(h));
    } else {
        int i = tid;
        double snr_lin = pow(10.0, 0.7);
        float nstd = (float)sqrt(1.0 / (2.0 * 2.0 * snr_lin));   // rate = 2
        float acc = 0.f;
#pragma unroll 4
        for (int t = 0; t < TAPSN; t++) {
            int idx = i + 49 - t;
            if (idx >= 0 && idx < CUN) acc += fir[t] * (noise[idx] * nstd);
        }
        nc[i] = acc;
        out_tail[i] = acc;
    }
}

__global__ void stats_reduce2(const float* __restrict__ part,
                              float* __restrict__ sum, float* __restrict__ sq, int Ncols)
{
    int c = blockIdx.x;
    int t = threadIdx.x;
    float s = part[((size_t)t * 2    ) * Ncols + c];
    float q = part[((size_t)t * 2 + 1) * Ncols + c];
#pragma unroll
    for (int o = 16; o > 0; o >>= 1) {
        s += __shfl_down_sync(0xFFFFFFFFu, s, o);
        q += __shfl_down_sync(0xFFFFFFFFu, q, o);
    }
    __shared__ float sh[64];
    int w = t >> 5, l = t & 31;
    if (l == 0) { sh[w] = s; sh[32 + w] = q; }
    __syncthreads();
    if (t == 0) {
        float S = 0.f, Q = 0.f;
        for (int i = 0; i < 8; i++) { S += sh[i]; Q += sh[32 + i]; }
        sum[c] = S; sq[c] = Q;
    }
}

__global__ void fold_kernel(const float* __restrict__ Wsrc, const float* __restrict__ bsrc,
                            const float* __restrict__ gam,  const float* __restrict__ bt,
                            const float* __restrict__ sum,  const float* __restrict__ sq,
                            __half* __restrict__ Whi, __half* __restrict__ Wlo,
                            float* __restrict__ bdst, int Kin)
{
    int j = blockIdx.x;
    int tid = threadIdx.x;  // 128
    const float invB = 1.0f / (float)B_ROWS;
    float partial = 0.f;
    for (int k = tid; k < Kin; k += 128) {
        float mu  = sum[k] * invB;
        float var = sq[k] * invB - mu * mu;
        float rs  = rsqrtf(var + 1e-5f);
        float s   = gam[k] * rs;
        float w   = Wsrc[(size_t)j * Kin + k];
        float wf  = w * s;
        __half h = __float2half_rn(wf);
        Whi[(size_t)j * Kin + k] = h;
        Wlo[(size_t)j * Kin + k] = __float2half_rn(wf - __half2float(h));
        partial += w * (bt[k] - mu * s);
    }
    __shared__ float sh[128];
    sh[tid] = partial; __syncthreads();
    for (int s = 64; s > 0; s >>= 1) { if (tid < s) sh[tid] += sh[tid + s]; __syncthreads(); }
    if (tid == 0) bdst[j] = bsrc[j] + sh[0];
}

// ================= shape A: CTA 256x128, 512 thr, 16 warps (4x4), warp 64x32 =====
// C = epi(A @ W^T + bias); A single fp16. TERMS=2: W = Wh+Wl; TERMS=1: W = Wh only.
// EPI: 0 -> fp32 out; 1 -> PReLU -> fp16 out. STATS: per-CTA column partials.
template <int EPI, bool STATS, int TERMS>
__global__ void __launch_bounds__(512, 1)
gemm_a(const __half* __restrict__ Ax,
       const __half* __restrict__ BH, const __half* __restrict__ BL,
       const float* __restrict__ bias,
       float* __restrict__ Cf, __half* __restrict__ Ch,
       int M, int N, int K, const float* __restrict__ alpha_ptr,
       float* __restrict__ part)
{
    extern __shared__ char smem[];
    float* bias_s = (float*)smem;                 // 128 f
    float* s_sm   = (float*)(smem + 1024);        // 4 x 128
    float* q_sm   = (float*)(smem + 3072);        // 4 x 128
    char*  stage0 = smem + A_HDR;

    const int tid = threadIdx.x;
    const int lane = tid & 31, wid = tid >> 5;
    const int wm = wid & 3, wn = wid >> 2;        // 4 x 4 warps, tile 64 x 32
    const int m0 = blockIdx.y * 256, n0 = blockIdx.x * 128;

    if (tid < 128) bias_s[tid] = bias[n0 + tid];

    float acc[4][4][4];
#pragma unroll
    for (int i = 0; i < 4; i++)
#pragma unroll
        for (int j = 0; j < 4; j++)
#pragma unroll
            for (int r = 0; r < 4; r++) acc[i][j][r] = 0.f;

    const int nit = K / KTT;
    constexpr int NCH = (TERMS == 2) ? 4 : 3;     // 512-thread chunks per stage

    auto load_stage = [&](int s, int k0) {
        uint32_t sb = s2u(stage0 + s * A_STAGE_B);
#pragma unroll
        for (int i = 0; i < NCH; i++) {
            int ch = tid + i * 512;               // 0..(NCH*512-1)
            uint32_t dst; const __half* g;
            if (ch < 1024) {                      // A: 256 rows x 4 chunks
                int r = ch >> 2, c = ch & 3;
                dst = sb + (A_A + r * RS) * 2 + c * 16;
                g = Ax + (size_t)(m0 + r) * K + k0 + c * 8;
            } else if (ch < 1536) {               // BH: 128 rows x 4
                int l = ch - 1024; int r = l >> 2, c = l & 3;
                dst = sb + (A_BH + r * RS) * 2 + c * 16;
                g = BH + (size_t)(n0 + r) * K + k0 + c * 8;
            } else {                              // BL (TERMS==2 only)
                int l = ch - 1536; int r = l >> 2, c = l & 3;
                dst = sb + (A_BL + r * RS) * 2 + c * 16;
                g = BL + (size_t)(n0 + r) * K + k0 + c * 8;
            }
            cpa16(dst, g);
        }
    };

    for (int s = 0; s < A_ST - 1; s++) {
        if (s < nit) load_stage(s, s * KTT);
        asm volatile("cp.async.commit_group;" ::: "memory");
    }

    const uint32_t aoff = (uint32_t)(((wm * 64 + (lane & 15)) * RS + (lane >> 4) * 8) * 2);
    const uint32_t boff = (uint32_t)(((wn * 32 + (lane & 7) + ((lane >> 4) << 3)) * RS
                                      + ((lane >> 3) & 1) * 8) * 2);

    for (int it = 0; it < nit; it++) {
        asm volatile("cp.async.wait_group %0;" :: "n"(A_ST - 2) : "memory");
        __syncthreads();
        int ns = it + A_ST - 1;
        if (ns < nit) load_stage(ns % A_ST, ns * KTT);
        asm volatile("cp.async.commit_group;" ::: "memory");

        uint32_t sb = s2u(stage0 + (it % A_ST) * A_STAGE_B);
#pragma unroll
        for (int k16 = 0; k16 < 2; k16++) {
            uint32_t ko = k16 * 32;
            uint32_t ah[4][4], b0[4][2];
#pragma unroll
            for (int i = 0; i < 4; i++)
                ldm4(ah[i], sb + A_A * 2 + aoff + i * 16 * RS * 2 + ko);
#pragma unroll
            for (int p = 0; p < 2; p++) {
                uint32_t t[4];
                ldm4(t, sb + A_BH * 2 + boff + p * 16 * RS * 2 + ko);
                b0[p*2][0] = t[0]; b0[p*2][1] = t[1]; b0[p*2+1][0] = t[2]; b0[p*2+1][1] = t[3];
            }
#pragma unroll
            for (int i = 0; i < 4; i++)
#pragma unroll
                for (int j = 0; j < 4; j++) mma_h(acc[i][j], ah[i], b0[j]);

            if (TERMS == 2) {
                uint32_t b1[4][2];
#pragma unroll
                for (int p = 0; p < 2; p++) {
                    uint32_t t[4];
                    ldm4(t, sb + A_BL * 2 + boff + p * 16 * RS * 2 + ko);
                    b1[p*2][0] = t[0]; b1[p*2][1] = t[1]; b1[p*2+1][0] = t[2]; b1[p*2+1][1] = t[3];
                }
#pragma unroll
                for (int i = 0; i < 4; i++)
#pragma unroll
                    for (int j = 0; j < 4; j++) mma_h(acc[i][j], ah[i], b1[j]);
            }
        }
    }

    // -------- epilogue --------
    const int qr = lane >> 2, qc = (lane & 3) * 2;
    float alpha = (EPI == 1) ? *alpha_ptr : 0.f;
    float cs0[4], cs1[4], cq0[4], cq1[4];
    if (STATS)
#pragma unroll
        for (int j = 0; j < 4; j++) { cs0[j] = cs1[j] = cq0[j] = cq1[j] = 0.f; }

#pragma unroll
    for (int i = 0; i < 4; i++) {
        int rl = wm * 64 + i * 16 + qr;
        size_t r0 = (size_t)(m0 + rl);
#pragma unroll
        for (int j = 0; j < 4; j++) {
            int cj = wn * 32 + j * 8 + qc;
            float b0 = bias_s[cj], b1 = bias_s[cj + 1];
            float v00 = acc[i][j][0] + b0, v01 = acc[i][j][1] + b1;
            float v10 = acc[i][j][2] + b0, v11 = acc[i][j][3] + b1;
            if (EPI == 1) {
                v00 = v00 > 0.f ? v00 : alpha * v00;
                v01 = v01 > 0.f ? v01 : alpha * v01;
                v10 = v10 > 0.f ? v10 : alpha * v10;
                v11 = v11 > 0.f ? v11 : alpha * v11;
            }
            if (STATS) {
                cs0[j] += v00 + v10;  cq0[j] += v00 * v00 + v10 * v10;
                cs1[j] += v01 + v11;  cq1[j] += v01 * v01 + v11 * v11;
            }
            size_t o0 = r0 * N + n0 + cj;
            size_t o1 = (r0 + 8) * N + n0 + cj;
            if (EPI == 0) {
                *(float2*)(Cf + o0) = make_float2(v00, v01);
                *(float2*)(Cf + o1) = make_float2(v10, v11);
            } else {
                *(uint32_t*)(Ch + o0) = pkh(v00, v01);
                *(uint32_t*)(Ch + o1) = pkh(v10, v11);
            }
        }
    }

    if (STATS) {
#pragma unroll
        for (int j = 0; j < 4; j++) {
#pragma unroll
            for (int o = 4; o <= 16; o <<= 1) {
                cs0[j] += __shfl_xor_sync(0xFFFFFFFFu, cs0[j], o);
                cs1[j] += __shfl_xor_sync(0xFFFFFFFFu, cs1[j], o);
                cq0[j] += __shfl_xor_sync(0xFFFFFFFFu, cq0[j], o);
                cq1[j] += __shfl_xor_sync(0xFFFFFFFFu, cq1[j], o);
            }
        }
        if (lane < 4) {
#pragma unroll
            for (int j = 0; j < 4; j++) {
                int cj = wn * 32 + j * 8 + lane * 2;
                s_sm[wm * 128 + cj]     = cs0[j];
                s_sm[wm * 128 + cj + 1] = cs1[j];
                q_sm[wm * 128 + cj]     = cq0[j];
                q_sm[wm * 128 + cj + 1] = cq1[j];
            }
        }
        __syncthreads();
        if (tid < 128) {
            float S = s_sm[tid] + s_sm[128 + tid] + s_sm[256 + tid] + s_sm[384 + tid];
            float Q = q_sm[tid] + q_sm[128 + tid] + q_sm[256 + tid] + q_sm[384 + tid];
            part[((size_t)blockIdx.y * 2    ) * N + n0 + tid] = S;
            part[((size_t)blockIdx.y * 2 + 1) * N + n0 + tid] = Q;
        }
    }
}

// ================= shape B (G2): CTA 128x256, 256 thr, rownorm+noise epilogue ====
__global__ void __launch_bounds__(256, 1)
gemm_b(const __half* __restrict__ Ax,
       const __half* __restrict__ BH, const __half* __restrict__ BL,
       const float* __restrict__ bias, __half* __restrict__ Ch,
       int M, int N, int K, const float* __restrict__ nc)
{
    extern __shared__ char smem[];
    float* bias_s = (float*)smem;
    float* nc_s   = (float*)(smem + 1024);
    float* rsq    = (float*)(smem + 2048);
    char*  stage0 = smem + B_HDR;

    const int tid = threadIdx.x;
    const int lane = tid & 31, wid = tid >> 5;
    const int wm = wid & 1, wn = wid >> 1;
    const int m0 = blockIdx.y * 128;

    bias_s[tid] = bias[tid];
    nc_s[tid] = nc[tid];

    float acc[4][8][4];
#pragma unroll
    for (int i = 0; i < 4; i++)
#pragma unroll
        for (int j = 0; j < 8; j++)
#pragma unroll
            for (int r = 0; r < 4; r++) acc[i][j][r] = 0.f;

    const int nit = K / KTT;

    auto load_stage = [&](int s, int k0) {
        uint32_t sb = s2u(stage0 + s * B_STAGE_B);
#pragma unroll
        for (int i = 0; i < 10; i++) {
            int ch = tid + i * 256;               // 0..2559
            uint32_t dst; const __half* g;
            if (ch < 512) {                       // A: 128 rows x 4
                int r = ch >> 2, c = ch & 3;
                dst = sb + (B_A + r * RS) * 2 + c * 16;
                g = Ax + (size_t)(m0 + r) * K + k0 + c * 8;
            } else if (ch < 1536) {               // BH: 256 rows x 4
                int l = ch - 512; int r = l >> 2, c = l & 3;
                dst = sb + (B_BH + r * RS) * 2 + c * 16;
                g = BH + (size_t)r * K + k0 + c * 8;
            } else {                              // BL
                int l = ch - 1536; int r = l >> 2, c = l & 3;
                dst = sb + (B_BL + r * RS) * 2 + c * 16;
                g = BL + (size_t)r * K + k0 + c * 8;
            }
            cpa16(dst, g);
        }
    };

    for (int s = 0; s < B_ST - 1; s++) {
        if (s < nit) load_stage(s, s * KTT);
        asm volatile("cp.async.commit_group;" ::: "memory");
    }

    const uint32_t aoff = (uint32_t)(((wm * 64 + (lane & 15)) * RS + (lane >> 4) * 8) * 2);
    const uint32_t boff = (uint32_t)(((wn * 64 + (lane & 7) + ((lane >> 4) << 3)) * RS
                                      + ((lane >> 3) & 1) * 8) * 2);

    for (int it = 0; it < nit; it++) {
        asm volatile("cp.async.wait_group %0;" :: "n"(B_ST - 2) : "memory");
        __syncthreads();
        int ns = it + B_ST - 1;
        if (ns < nit) load_stage(ns % B_ST, ns * KTT);
        asm volatile("cp.async.commit_group;" ::: "memory");

        uint32_t sb = s2u(stage0 + (it % B_ST) * B_STAGE_B);
#pragma unroll
        for (int k16 = 0; k16 < 2; k16++) {
            uint32_t ko = k16 * 32;
            uint32_t ah[4][4], bh[8][2];
#pragma unroll
            for (int i = 0; i < 4; i++)
                ldm4(ah[i], sb + B_A * 2 + aoff + i * 16 * RS * 2 + ko);
#pragma unroll
            for (int p = 0; p < 4; p++) {
                uint32_t t[4];
                ldm4(t, sb + B_BH * 2 + boff + p * 16 * RS * 2 + ko);
                bh[p*2][0] = t[0]; bh[p*2][1] = t[1]; bh[p*2+1][0] = t[2]; bh[p*2+1][1] = t[3];
            }
#pragma unroll
            for (int i = 0; i < 4; i++)
#pragma unroll
                for (int j = 0; j < 8; j++) mma_h(acc[i][j], ah[i], bh[j]);

            uint32_t bl[8][2];
#pragma unroll
            for (int p = 0; p < 4; p++) {
                uint32_t t[4];
                ldm4(t, sb + B_BL * 2 + boff + p * 16 * RS * 2 + ko);
                bl[p*2][0] = t[0]; bl[p*2][1] = t[1]; bl[p*2+1][0] = t[2]; bl[p*2+1][1] = t[3];
            }
#pragma unroll
            for (int i = 0; i < 4; i++)
#pragma unroll
                for (int j = 0; j < 8; j++) mma_h(acc[i][j], ah[i], bl[j]);
        }
    }

    const int qr = lane >> 2, qc = (lane & 3) * 2;
#pragma unroll
    for (int i = 0; i < 4; i++)
#pragma unroll
        for (int j = 0; j < 8; j++) {
            int cj = wn * 64 + j * 8 + qc;
            acc[i][j][0] += bias_s[cj];     acc[i][j][1] += bias_s[cj + 1];
            acc[i][j][2] += bias_s[cj];     acc[i][j][3] += bias_s[cj + 1];
        }

#pragma unroll
    for (int i = 0; i < 4; i++) {
        float s0 = 0.f, s1 = 0.f;
#pragma unroll
        for (int j = 0; j < 8; j++) {
            s0 += acc[i][j][0] * acc[i][j][0] + acc[i][j][1] * acc[i][j][1];
            s1 += acc[i][j][2] * acc[i][j][2] + acc[i][j][3] * acc[i][j][3];
        }
        s0 += __shfl_xor_sync(0xFFFFFFFFu, s0, 1);
        s0 += __shfl_xor_sync(0xFFFFFFFFu, s0, 2);
        s1 += __shfl_xor_sync(0xFFFFFFFFu, s1, 1);
        s1 += __shfl_xor_sync(0xFFFFFFFFu, s1, 2);
        if ((lane & 3) == 0) {
            int rl = wm * 64 + i * 16 + qr;
            rsq[wn * 128 + rl]     = s0;
            rsq[wn * 128 + rl + 8] = s1;
        }
    }
    __syncthreads();
#pragma unroll
    for (int i = 0; i < 4; i++) {
        int rl = wm * 64 + i * 16 + qr;
        float t0 = rsq[rl]     + rsq[128 + rl]     + rsq[256 + rl]     + rsq[384 + rl];
        float t1 = rsq[rl + 8] + rsq[128 + rl + 8] + rsq[256 + rl + 8] + rsq[384 + rl + 8];
        float sc0 = 16.0f * rsqrtf(t0);   // sqrt(CU) = 16
        float sc1 = 16.0f * rsqrtf(t1);
        size_t r0 = (size_t)(m0 + rl);
#pragma unroll
        for (int j = 0; j < 8; j++) {
            int cj = wn * 64 + j * 8 + qc;
            float u00 = acc[i][j][0] * sc0 + nc_s[cj];
            float u01 = acc[i][j][1] * sc0 + nc_s[cj + 1];
            float u10 = acc[i][j][2] * sc1 + nc_s[cj];
            float u11 = acc[i][j][3] * sc1 + nc_s[cj + 1];
            size_t o0 = r0 * N + cj;
            size_t o1 = (r0 + 8) * N + cj;
            *(uint32_t*)(Ch + o0) = pkh(u00, u01);
            *(uint32_t*)(Ch + o1) = pkh(u10, u11);
        }
    }
}

// --------------------------------------------------------------------------------
extern "C" void kernel_launch(void* const* d_in, const int* in_sizes, int n_in,
                              void* d_out, int out_size)
{
    const float* x    = (const float*)d_in[0];
    const float* nz   = (const float*)d_in[1];
    const float* W1   = (const float*)d_in[2];
    const float* b1   = (const float*)d_in[3];
    const float* a1   = (const float*)d_in[4];
    const float* gm1  = (const float*)d_in[5];
    const float* bt1  = (const float*)d_in[6];
    const float* W2   = (const float*)d_in[7];
    const float* b2   = (const float*)d_in[8];
    const float* W3   = (const float*)d_in[9];
    const float* b3   = (const float*)d_in[10];
    const float* a2   = (const float*)d_in[11];
    const float* gm2  = (const float*)d_in[12];
    const float* bt2  = (const float*)d_in[13];
    const float* W4   = (const float*)d_in[14];
    const float* b4   = (const float*)d_in[15];
    const float* fir  = (const float*)d_in[16];
    float* out = (float*)d_out;

    __half *x16, *h1, *yc, *dd;
    __half *W1h, *W1l, *W2h, *W2l, *W3h, *W3l, *W4h, *W4l;
    float *b2f, *b4f, *st, *part, *nc;
    cudaGetSymbolAddress((void**)&x16, g_x16);
    cudaGetSymbolAddress((void**)&h1,  g_h1);
    cudaGetSymbolAddress((void**)&yc,  g_yc);
    cudaGetSymbolAddress((void**)&dd,  g_dd);
    cudaGetSymbolAddress((void**)&W1h, g_W1h);  cudaGetSymbolAddress((void**)&W1l, g_W1l);
    cudaGetSymbolAddress((void**)&W2h, g_W2h);  cudaGetSymbolAddress((void**)&W2l, g_W2l);
    cudaGetSymbolAddress((void**)&W3h, g_W3h);  cudaGetSymbolAddress((void**)&W3l, g_W3l);
    cudaGetSymbolAddress((void**)&W4h, g_W4h);  cudaGetSymbolAddress((void**)&W4l, g_W4l);
    cudaGetSymbolAddress((void**)&b2f, g_b2f);
    cudaGetSymbolAddress((void**)&b4f, g_b4f);
    cudaGetSymbolAddress((void**)&st,  g_stats);
    cudaGetSymbolAddress((void**)&part,g_part);
    cudaGetSymbolAddress((void**)&nc,  g_nc);

    const int SMEM_A = A_HDR + A_ST * A_STAGE_B;   // 212992
    const int SMEM_B = B_HDR + B_ST * B_STAGE_B;   // 208896
    cudaFuncSetAttribute((const void*)gemm_a<0, false, 1>,
                         cudaFuncAttributeMaxDynamicSharedMemorySize, SMEM_A);
    cudaFuncSetAttribute((const void*)gemm_a<1, true, 1>,
                         cudaFuncAttributeMaxDynamicSharedMemorySize, SMEM_A);
    cudaFuncSetAttribute((const void*)gemm_a<1, true, 2>,
                         cudaFuncAttributeMaxDynamicSharedMemorySize, SMEM_A);
    cudaFuncSetAttribute((const void*)gemm_b,
                         cudaFuncAttributeMaxDynamicSharedMemorySize, SMEM_B);

    // 0) fused prep (x -> fp16, W1/W3 fp16 hi/lo splits, FIR noise)
    prep_kernel<<<SPLITX_BLOCKS + W1_BLOCKS + W3_BLOCKS + 1, 256>>>(
        x, x16, W1, W1h, W1l, W3, W3h, W3l, nz, fir, nc,
        out + (size_t)B_ROWS * BLK);

    // 1) h1 = prelu(x @ W1^T + b1) -> fp16, fused BN1 partials. SINGLE-term W1.
    gemm_a<1, true, 1><<<dim3(BLK / 128, B_ROWS / 256), 512, SMEM_A>>>(
        x16, W1h, W1l, b1, nullptr, h1, B_ROWS, BLK, BLK, a1, part);

    // 2) BN1 reduce + fold into W2 (fp16 hi/lo)
    stats_reduce2<<<BLK, 256>>>(part, st, st + BLK, BLK);
    fold_kernel<<<CUN, 128>>>(W2, b2, gm1, bt1, st, st + BLK, W2h, W2l, b2f, BLK);

    // 3) yc = 16*(h1_bn @ W2^T + b2)/||row|| + noise -> fp16 (two-term W2)
    gemm_b<<<dim3(1, B_ROWS / 128), 256, SMEM_B>>>(
        h1, W2h, W2l, b2f, yc, B_ROWS, CUN, BLK, nc);

    // 4) d = prelu(yc @ W3^T + b3) -> fp16, fused BN2 partials (two-term W3)
    gemm_a<1, true, 2><<<dim3(BLK / 128, B_ROWS / 256), 512, SMEM_A>>>(
        yc, W3h, W3l, b3, nullptr, dd, B_ROWS, BLK, CUN, a2, part);

    // 5) BN2 reduce + fold into W4
    stats_reduce2<<<BLK, 256>>>(part, st + 2 * BLK, st + 3 * BLK, BLK);
    fold_kernel<<<BLK, 128>>>(W4, b4, gm2, bt2, st + 2 * BLK, st + 3 * BLK, W4h, W4l, b4f, BLK);

    // 6) out = d_bn @ W4^T + b4 (fp32). SINGLE-term W4.
    gemm_a<0, false, 1><<<dim3(BLK / 128, B_ROWS / 256), 512, SMEM_A>>>(
        dd, W4h, W4l, b4f, out, nullptr, B_ROWS, BLK, BLK, nullptr, nullptr);

    (void)in_sizes; (void)n_in; (void)out_size;
}

// round 15
// speedup vs baseline: 4.7468x; 1.1576x over previous
#include <cuda_runtime.h>
#include <cuda_fp16.h>
#include <math.h>
#include <stdint.h>

#define B_ROWS 65536
#define BLK    512
#define CUN    256
#define TAPSN  100

#define KTT    32
#define RS     40                         // padded SMEM row stride (elems) -> 80 B

// ---- shape A (G1/G3/G4): CTA 256x128, 512 thr, warp 64x32, A single fp16 ----
#define A_ST   5
#define A_A    0
#define A_BH   (256 * RS)
#define A_BL   (384 * RS)
#define A_STAGE_B (512 * RS * 2)          // 40960
#define A_HDR  8192

// ---- shape B (G2 rownorm): CTA 128x256, 256 thr, warp 64x64 ----
#define B_ST   4
#define B_A    0
#define B_BH   (128 * RS)
#define B_BL   (384 * RS)
#define B_STAGE_B (640 * RS * 2)          // 51200
#define B_HDR  4096

// ---------------- device scratch ----------------
static __device__ __half g_x16[(size_t)B_ROWS * BLK];
static __device__ __half g_h1 [(size_t)B_ROWS * BLK];
static __device__ __half g_yc [(size_t)B_ROWS * CUN];
static __device__ __half g_dd [(size_t)B_ROWS * BLK];
static __device__ __half g_W1h[BLK * BLK], g_W1l[BLK * BLK];
static __device__ __half g_W2h[CUN * BLK], g_W2l[CUN * BLK];
static __device__ __half g_W3h[BLK * CUN], g_W3l[BLK * CUN];
static __device__ __half g_W4h[BLK * BLK], g_W4l[BLK * BLK];
static __device__ float g_b2f[CUN], g_b4f[BLK];
static __device__ float g_stats[4 * BLK];
static __device__ float g_part [256 * 2 * BLK];   // [mblock][2][512]
static __device__ float g_nc  [CUN];

// ---------------- helpers ----------------
__device__ __forceinline__ uint32_t s2u(const void* p) {
    return (uint32_t)__cvta_generic_to_shared(p);
}
__device__ __forceinline__ void cpa16(uint32_t d, const void* s) {
    asm volatile("cp.async.cg.shared.global [%0], [%1], 16;" :: "r"(d), "l"(s));
}
__device__ __forceinline__ void ldm4(uint32_t* f, uint32_t a) {
    asm volatile("ldmatrix.sync.aligned.m8n8.x4.shared.b16 {%0,%1,%2,%3}, [%4];"
                 : "=r"(f[0]), "=r"(f[1]), "=r"(f[2]), "=r"(f[3]) : "r"(a));
}
__device__ __forceinline__ void mma_h(float* d, const uint32_t* a, const uint32_t* b) {
    asm volatile("mma.sync.aligned.m16n8k16.row.col.f32.f16.f16.f32 "
                 "{%0,%1,%2,%3}, {%4,%5,%6,%7}, {%8,%9}, {%0,%1,%2,%3};"
                 : "+f"(d[0]), "+f"(d[1]), "+f"(d[2]), "+f"(d[3])
                 : "r"(a[0]), "r"(a[1]), "r"(a[2]), "r"(a[3]), "r"(b[0]), "r"(b[1]));
}
__device__ __forceinline__ uint32_t pkh(float a, float b) {
    __half2 h = __floats2half2_rn(a, b);
    return *(uint32_t*)&h;
}

// ---------------- fused prep: x->fp16 | W1 split | W3 split | FIR noise ---------
#define SPLITX_BLOCKS 32768
#define W1_BLOCKS     1024
#define W3_BLOCKS     512
__global__ void prep_kernel(const float* __restrict__ x, __half* __restrict__ x16,
                            const float* __restrict__ W1,
                            __half* __restrict__ W1h, __half* __restrict__ W1l,
                            const float* __restrict__ W3,
                            __half* __restrict__ W3h, __half* __restrict__ W3l,
                            const float* __restrict__ noise, const float* __restrict__ fir,
                            float* __restrict__ nc, float* __restrict__ out_tail)
{
    int bid = blockIdx.x, tid = threadIdx.x;
    if (bid < SPLITX_BLOCKS) {
        int i = bid * 256 + tid;
        float4 v = ((const float4*)x)[i];
        ((uint2*)x16)[i] = make_uint2(pkh(v.x, v.y), pkh(v.z, v.w));
    } else if (bid < SPLITX_BLOCKS + W1_BLOCKS) {
        int i = (bid - SPLITX_BLOCKS) * 256 + tid;
        float v = W1[i];
        __half h = __float2half_rn(v);
        W1h[i] = h;
        W1l[i] = __float2half_rn(v - __half2float(h));
    } else if (bid < SPLITX_BLOCKS + W1_BLOCKS + W3_BLOCKS) {
        int i = (bid - SPLITX_BLOCKS - W1_BLOCKS) * 256 + tid;
        float v = W3[i];
        __half h = __float2half_rn(v);
        W3h[i] = h;
        W3l[i] = __float2half_rn(v - __half2float(h));
    } else {
        int i = tid;
        double snr_lin = pow(10.0, 0.7);
        float nstd = (float)sqrt(1.0 / (2.0 * 2.0 * snr_lin));   // rate = 2
        float acc = 0.f;
#pragma unroll 4
        for (int t = 0; t < TAPSN; t++) {
            int idx = i + 49 - t;
            if (idx >= 0 && idx < CUN) acc += fir[t] * (noise[idx] * nstd);
        }
        nc[i] = acc;
        out_tail[i] = acc;
    }
}

__global__ void stats_reduce2(const float* __restrict__ part,
                              float* __restrict__ sum, float* __restrict__ sq, int Ncols)
{
    int c = blockIdx.x;
    int t = threadIdx.x;
    float s = part[((size_t)t * 2    ) * Ncols + c];
    float q = part[((size_t)t * 2 + 1) * Ncols + c];
#pragma unroll
    for (int o = 16; o > 0; o >>= 1) {
        s += __shfl_down_sync(0xFFFFFFFFu, s, o);
        q += __shfl_down_sync(0xFFFFFFFFu, q, o);
    }
    __shared__ float sh[64];
    int w = t >> 5, l = t & 31;
    if (l == 0) { sh[w] = s; sh[32 + w] = q; }
    __syncthreads();
    if (t == 0) {
        float S = 0.f, Q = 0.f;
        for (int i = 0; i < 8; i++) { S += sh[i]; Q += sh[32 + i]; }
        sum[c] = S; sq[c] = Q;
    }
}

__global__ void fold_kernel(const float* __restrict__ Wsrc, const float* __restrict__ bsrc,
                            const float* __restrict__ gam,  const float* __restrict__ bt,
                            const float* __restrict__ sum,  const float* __restrict__ sq,
                            __half* __restrict__ Whi, __half* __restrict__ Wlo,
                            float* __restrict__ bdst, int Kin)
{
    int j = blockIdx.x;
    int tid = threadIdx.x;  // 128
    const float invB = 1.0f / (float)B_ROWS;
    float partial = 0.f;
    for (int k = tid; k < Kin; k += 128) {
        float mu  = sum[k] * invB;
        float var = sq[k] * invB - mu * mu;
        float rs  = rsqrtf(var + 1e-5f);
        float s   = gam[k] * rs;
        float w   = Wsrc[(size_t)j * Kin + k];
        float wf  = w * s;
        __half h = __float2half_rn(wf);
        Whi[(size_t)j * Kin + k] = h;
        Wlo[(size_t)j * Kin + k] = __float2half_rn(wf - __half2float(h));
        partial += w * (bt[k] - mu * s);
    }
    __shared__ float sh[128];
    sh[tid] = partial; __syncthreads();
    for (int s = 64; s > 0; s >>= 1) { if (tid < s) sh[tid] += sh[tid + s]; __syncthreads(); }
    if (tid == 0) bdst[j] = bsrc[j] + sh[0];
}

// ================= shape A: CTA 256x128, 512 thr, 16 warps (4x4), warp 64x32 =====
// C = epi(A @ W^T + bias); A single fp16. TERMS=2: W = Wh+Wl; TERMS=1: W = Wh only.
// EPI: 0 -> fp32 out; 1 -> PReLU -> fp16 out. STATS: per-CTA column partials.
template <int EPI, bool STATS, int TERMS>
__global__ void __launch_bounds__(512, 1)
gemm_a(const __half* __restrict__ Ax,
       const __half* __restrict__ BH, const __half* __restrict__ BL,
       const float* __restrict__ bias,
       float* __restrict__ Cf, __half* __restrict__ Ch,
       int M, int N, int K, const float* __restrict__ alpha_ptr,
       float* __restrict__ part)
{
    extern __shared__ char smem[];
    float* bias_s = (float*)smem;                 // 128 f
    float* s_sm   = (float*)(smem + 1024);        // 4 x 128
    float* q_sm   = (float*)(smem + 3072);        // 4 x 128
    char*  stage0 = smem + A_HDR;

    const int tid = threadIdx.x;
    const int lane = tid & 31, wid = tid >> 5;
    const int wm = wid & 3, wn = wid >> 2;        // 4 x 4 warps, tile 64 x 32
    const int m0 = blockIdx.y * 256, n0 = blockIdx.x * 128;

    if (tid < 128) bias_s[tid] = bias[n0 + tid];

    float acc[4][4][4];
#pragma unroll
    for (int i = 0; i < 4; i++)
#pragma unroll
        for (int j = 0; j < 4; j++)
#pragma unroll
            for (int r = 0; r < 4; r++) acc[i][j][r] = 0.f;

    const int nit = K / KTT;
    constexpr int NCH = (TERMS == 2) ? 4 : 3;     // 512-thread chunks per stage

    auto load_stage = [&](int s, int k0) {
        uint32_t sb = s2u(stage0 + s * A_STAGE_B);
#pragma unroll
        for (int i = 0; i < NCH; i++) {
            int ch = tid + i * 512;               // 0..(NCH*512-1)
            uint32_t dst; const __half* g;
            if (ch < 1024) {                      // A: 256 rows x 4 chunks
                int r = ch >> 2, c = ch & 3;
                dst = sb + (A_A + r * RS) * 2 + c * 16;
                g = Ax + (size_t)(m0 + r) * K + k0 + c * 8;
            } else if (ch < 1536) {               // BH: 128 rows x 4
                int l = ch - 1024; int r = l >> 2, c = l & 3;
                dst = sb + (A_BH + r * RS) * 2 + c * 16;
                g = BH + (size_t)(n0 + r) * K + k0 + c * 8;
            } else {                              // BL (TERMS==2 only)
                int l = ch - 1536; int r = l >> 2, c = l & 3;
                dst = sb + (A_BL + r * RS) * 2 + c * 16;
                g = BL + (size_t)(n0 + r) * K + k0 + c * 8;
            }
            cpa16(dst, g);
        }
    };

    for (int s = 0; s < A_ST - 1; s++) {
        if (s < nit) load_stage(s, s * KTT);
        asm volatile("cp.async.commit_group;" ::: "memory");
    }

    const uint32_t aoff = (uint32_t)(((wm * 64 + (lane & 15)) * RS + (lane >> 4) * 8) * 2);
    const uint32_t boff = (uint32_t)(((wn * 32 + (lane & 7) + ((lane >> 4) << 3)) * RS
                                      + ((lane >> 3) & 1) * 8) * 2);

    for (int it = 0; it < nit; it++) {
        asm volatile("cp.async.wait_group %0;" :: "n"(A_ST - 2) : "memory");
        __syncthreads();
        int ns = it + A_ST - 1;
        if (ns < nit) load_stage(ns % A_ST, ns * KTT);
        asm volatile("cp.async.commit_group;" ::: "memory");

        uint32_t sb = s2u(stage0 + (it % A_ST) * A_STAGE_B);
#pragma unroll
        for (int k16 = 0; k16 < 2; k16++) {
            uint32_t ko = k16 * 32;
            uint32_t ah[4][4], b0[4][2];
#pragma unroll
            for (int i = 0; i < 4; i++)
                ldm4(ah[i], sb + A_A * 2 + aoff + i * 16 * RS * 2 + ko);
#pragma unroll
            for (int p = 0; p < 2; p++) {
                uint32_t t[4];
                ldm4(t, sb + A_BH * 2 + boff + p * 16 * RS * 2 + ko);
                b0[p*2][0] = t[0]; b0[p*2][1] = t[1]; b0[p*2+1][0] = t[2]; b0[p*2+1][1] = t[3];
            }
#pragma unroll
            for (int i = 0; i < 4; i++)
#pragma unroll
                for (int j = 0; j < 4; j++) mma_h(acc[i][j], ah[i], b0[j]);

            if (TERMS == 2) {
                uint32_t b1[4][2];
#pragma unroll
                for (int p = 0; p < 2; p++) {
                    uint32_t t[4];
                    ldm4(t, sb + A_BL * 2 + boff + p * 16 * RS * 2 + ko);
                    b1[p*2][0] = t[0]; b1[p*2][1] = t[1]; b1[p*2+1][0] = t[2]; b1[p*2+1][1] = t[3];
                }
#pragma unroll
                for (int i = 0; i < 4; i++)
#pragma unroll
                    for (int j = 0; j < 4; j++) mma_h(acc[i][j], ah[i], b1[j]);
            }
        }
    }

    // -------- epilogue --------
    const int qr = lane >> 2, qc = (lane & 3) * 2;
    float alpha = (EPI == 1) ? *alpha_ptr : 0.f;
    float cs0[4], cs1[4], cq0[4], cq1[4];
    if (STATS)
#pragma unroll
        for (int j = 0; j < 4; j++) { cs0[j] = cs1[j] = cq0[j] = cq1[j] = 0.f; }

#pragma unroll
    for (int i = 0; i < 4; i++) {
        int rl = wm * 64 + i * 16 + qr;
        size_t r0 = (size_t)(m0 + rl);
#pragma unroll
        for (int j = 0; j < 4; j++) {
            int cj = wn * 32 + j * 8 + qc;
            float b0 = bias_s[cj], b1 = bias_s[cj + 1];
            float v00 = acc[i][j][0] + b0, v01 = acc[i][j][1] + b1;
            float v10 = acc[i][j][2] + b0, v11 = acc[i][j][3] + b1;
            if (EPI == 1) {
                v00 = v00 > 0.f ? v00 : alpha * v00;
                v01 = v01 > 0.f ? v01 : alpha * v01;
                v10 = v10 > 0.f ? v10 : alpha * v10;
                v11 = v11 > 0.f ? v11 : alpha * v11;
            }
            if (STATS) {
                cs0[j] += v00 + v10;  cq0[j] += v00 * v00 + v10 * v10;
                cs1[j] += v01 + v11;  cq1[j] += v01 * v01 + v11 * v11;
            }
            size_t o0 = r0 * N + n0 + cj;
            size_t o1 = (r0 + 8) * N + n0 + cj;
            if (EPI == 0) {
                *(float2*)(Cf + o0) = make_float2(v00, v01);
                *(float2*)(Cf + o1) = make_float2(v10, v11);
            } else {
                *(uint32_t*)(Ch + o0) = pkh(v00, v01);
                *(uint32_t*)(Ch + o1) = pkh(v10, v11);
            }
        }
    }

    if (STATS) {
#pragma unroll
        for (int j = 0; j < 4; j++) {
#pragma unroll
            for (int o = 4; o <= 16; o <<= 1) {
                cs0[j] += __shfl_xor_sync(0xFFFFFFFFu, cs0[j], o);
                cs1[j] += __shfl_xor_sync(0xFFFFFFFFu, cs1[j], o);
                cq0[j] += __shfl_xor_sync(0xFFFFFFFFu, cq0[j], o);
                cq1[j] += __shfl_xor_sync(0xFFFFFFFFu, cq1[j], o);
            }
        }
        if (lane < 4) {
#pragma unroll
            for (int j = 0; j < 4; j++) {
                int cj = wn * 32 + j * 8 + lane * 2;
                s_sm[wm * 128 + cj]     = cs0[j];
                s_sm[wm * 128 + cj + 1] = cs1[j];
                q_sm[wm * 128 + cj]     = cq0[j];
                q_sm[wm * 128 + cj + 1] = cq1[j];
            }
        }
        __syncthreads();
        if (tid < 128) {
            float S = s_sm[tid] + s_sm[128 + tid] + s_sm[256 + tid] + s_sm[384 + tid];
            float Q = q_sm[tid] + q_sm[128 + tid] + q_sm[256 + tid] + q_sm[384 + tid];
            part[((size_t)blockIdx.y * 2    ) * N + n0 + tid] = S;
            part[((size_t)blockIdx.y * 2 + 1) * N + n0 + tid] = Q;
        }
    }
}

// ================= shape B (G2): CTA 128x256, 256 thr, rownorm+noise epilogue ====
// TERMS=2: W = Wh+Wl; TERMS=1: W = Wh only (BL chunks and MMAs skipped).
template <int TERMS>
__global__ void __launch_bounds__(256, 1)
gemm_b(const __half* __restrict__ Ax,
       const __half* __restrict__ BH, const __half* __restrict__ BL,
       const float* __restrict__ bias, __half* __restrict__ Ch,
       int M, int N, int K, const float* __restrict__ nc)
{
    extern __shared__ char smem[];
    float* bias_s = (float*)smem;
    float* nc_s   = (float*)(smem + 1024);
    float* rsq    = (float*)(smem + 2048);
    char*  stage0 = smem + B_HDR;

    const int tid = threadIdx.x;
    const int lane = tid & 31, wid = tid >> 5;
    const int wm = wid & 1, wn = wid >> 1;
    const int m0 = blockIdx.y * 128;

    bias_s[tid] = bias[tid];
    nc_s[tid] = nc[tid];

    float acc[4][8][4];
#pragma unroll
    for (int i = 0; i < 4; i++)
#pragma unroll
        for (int j = 0; j < 8; j++)
#pragma unroll
            for (int r = 0; r < 4; r++) acc[i][j][r] = 0.f;

    const int nit = K / KTT;
    constexpr int NCH = (TERMS == 2) ? 10 : 6;    // 256-thread chunks per stage

    auto load_stage = [&](int s, int k0) {
        uint32_t sb = s2u(stage0 + s * B_STAGE_B);
#pragma unroll
        for (int i = 0; i < NCH; i++) {
            int ch = tid + i * 256;
            uint32_t dst; const __half* g;
            if (ch < 512) {                       // A: 128 rows x 4
                int r = ch >> 2, c = ch & 3;
                dst = sb + (B_A + r * RS) * 2 + c * 16;
                g = Ax + (size_t)(m0 + r) * K + k0 + c * 8;
            } else if (ch < 1536) {               // BH: 256 rows x 4
                int l = ch - 512; int r = l >> 2, c = l & 3;
                dst = sb + (B_BH + r * RS) * 2 + c * 16;
                g = BH + (size_t)r * K + k0 + c * 8;
            } else {                              // BL (TERMS==2 only)
                int l = ch - 1536; int r = l >> 2, c = l & 3;
                dst = sb + (B_BL + r * RS) * 2 + c * 16;
                g = BL + (size_t)r * K + k0 + c * 8;
            }
            cpa16(dst, g);
        }
    };

    for (int s = 0; s < B_ST - 1; s++) {
        if (s < nit) load_stage(s, s * KTT);
        asm volatile("cp.async.commit_group;" ::: "memory");
    }

    const uint32_t aoff = (uint32_t)(((wm * 64 + (lane & 15)) * RS + (lane >> 4) * 8) * 2);
    const uint32_t boff = (uint32_t)(((wn * 64 + (lane & 7) + ((lane >> 4) << 3)) * RS
                                      + ((lane >> 3) & 1) * 8) * 2);

    for (int it = 0; it < nit; it++) {
        asm volatile("cp.async.wait_group %0;" :: "n"(B_ST - 2) : "memory");
        __syncthreads();
        int ns = it + B_ST - 1;
        if (ns < nit) load_stage(ns % B_ST, ns * KTT);
        asm volatile("cp.async.commit_group;" ::: "memory");

        uint32_t sb = s2u(stage0 + (it % B_ST) * B_STAGE_B);
#pragma unroll
        for (int k16 = 0; k16 < 2; k16++) {
            uint32_t ko = k16 * 32;
            uint32_t ah[4][4], bh[8][2];
#pragma unroll
            for (int i = 0; i < 4; i++)
                ldm4(ah[i], sb + B_A * 2 + aoff + i * 16 * RS * 2 + ko);
#pragma unroll
            for (int p = 0; p < 4; p++) {
                uint32_t t[4];
                ldm4(t, sb + B_BH * 2 + boff + p * 16 * RS * 2 + ko);
                bh[p*2][0] = t[0]; bh[p*2][1] = t[1]; bh[p*2+1][0] = t[2]; bh[p*2+1][1] = t[3];
            }
#pragma unroll
            for (int i = 0; i < 4; i++)
#pragma unroll
                for (int j = 0; j < 8; j++) mma_h(acc[i][j], ah[i], bh[j]);

            if (TERMS == 2) {
                uint32_t bl[8][2];
#pragma unroll
                for (int p = 0; p < 4; p++) {
                    uint32_t t[4];
                    ldm4(t, sb + B_BL * 2 + boff + p * 16 * RS * 2 + ko);
                    bl[p*2][0] = t[0]; bl[p*2][1] = t[1]; bl[p*2+1][0] = t[2]; bl[p*2+1][1] = t[3];
                }
#pragma unroll
                for (int i = 0; i < 4; i++)
#pragma unroll
                    for (int j = 0; j < 8; j++) mma_h(acc[i][j], ah[i], bl[j]);
            }
        }
    }

    const int qr = lane >> 2, qc = (lane & 3) * 2;
#pragma unroll
    for (int i = 0; i < 4; i++)
#pragma unroll
        for (int j = 0; j < 8; j++) {
            int cj = wn * 64 + j * 8 + qc;
            acc[i][j][0] += bias_s[cj];     acc[i][j][1] += bias_s[cj + 1];
            acc[i][j][2] += bias_s[cj];     acc[i][j][3] += bias_s[cj + 1];
        }

#pragma unroll
    for (int i = 0; i < 4; i++) {
        float s0 = 0.f, s1 = 0.f;
#pragma unroll
        for (int j = 0; j < 8; j++) {
            s0 += acc[i][j][0] * acc[i][j][0] + acc[i][j][1] * acc[i][j][1];
            s1 += acc[i][j][2] * acc[i][j][2] + acc[i][j][3] * acc[i][j][3];
        }
        s0 += __shfl_xor_sync(0xFFFFFFFFu, s0, 1);
        s0 += __shfl_xor_sync(0xFFFFFFFFu, s0, 2);
        s1 += __shfl_xor_sync(0xFFFFFFFFu, s1, 1);
        s1 += __shfl_xor_sync(0xFFFFFFFFu, s1, 2);
        if ((lane & 3) == 0) {
            int rl = wm * 64 + i * 16 + qr;
            rsq[wn * 128 + rl]     = s0;
            rsq[wn * 128 + rl + 8] = s1;
        }
    }
    __syncthreads();
#pragma unroll
    for (int i = 0; i < 4; i++) {
        int rl = wm * 64 + i * 16 + qr;
        float t0 = rsq[rl]     + rsq[128 + rl]     + rsq[256 + rl]     + rsq[384 + rl];
        float t1 = rsq[rl + 8] + rsq[128 + rl + 8] + rsq[256 + rl + 8] + rsq[384 + rl + 8];
        float sc0 = 16.0f * rsqrtf(t0);   // sqrt(CU) = 16
        float sc1 = 16.0f * rsqrtf(t1);
        size_t r0 = (size_t)(m0 + rl);
#pragma unroll
        for (int j = 0; j < 8; j++) {
            int cj = wn * 64 + j * 8 + qc;
            float u00 = acc[i][j][0] * sc0 + nc_s[cj];
            float u01 = acc[i][j][1] * sc0 + nc_s[cj + 1];
            float u10 = acc[i][j][2] * sc1 + nc_s[cj];
            float u11 = acc[i][j][3] * sc1 + nc_s[cj + 1];
            size_t o0 = r0 * N + cj;
            size_t o1 = (r0 + 8) * N + cj;
            *(uint32_t*)(Ch + o0) = pkh(u00, u01);
            *(uint32_t*)(Ch + o1) = pkh(u10, u11);
        }
    }
}

// --------------------------------------------------------------------------------
extern "C" void kernel_launch(void* const* d_in, const int* in_sizes, int n_in,
                              void* d_out, int out_size)
{
    const float* x    = (const float*)d_in[0];
    const float* nz   = (const float*)d_in[1];
    const float* W1   = (const float*)d_in[2];
    const float* b1   = (const float*)d_in[3];
    const float* a1   = (const float*)d_in[4];
    const float* gm1  = (const float*)d_in[5];
    const float* bt1  = (const float*)d_in[6];
    const float* W2   = (const float*)d_in[7];
    const float* b2   = (const float*)d_in[8];
    const float* W3   = (const float*)d_in[9];
    const float* b3   = (const float*)d_in[10];
    const float* a2   = (const float*)d_in[11];
    const float* gm2  = (const float*)d_in[12];
    const float* bt2  = (const float*)d_in[13];
    const float* W4   = (const float*)d_in[14];
    const float* b4   = (const float*)d_in[15];
    const float* fir  = (const float*)d_in[16];
    float* out = (float*)d_out;

    __half *x16, *h1, *yc, *dd;
    __half *W1h, *W1l, *W2h, *W2l, *W3h, *W3l, *W4h, *W4l;
    float *b2f, *b4f, *st, *part, *nc;
    cudaGetSymbolAddress((void**)&x16, g_x16);
    cudaGetSymbolAddress((void**)&h1,  g_h1);
    cudaGetSymbolAddress((void**)&yc,  g_yc);
    cudaGetSymbolAddress((void**)&dd,  g_dd);
    cudaGetSymbolAddress((void**)&W1h, g_W1h);  cudaGetSymbolAddress((void**)&W1l, g_W1l);
    cudaGetSymbolAddress((void**)&W2h, g_W2h);  cudaGetSymbolAddress((void**)&W2l, g_W2l);
    cudaGetSymbolAddress((void**)&W3h, g_W3h);  cudaGetSymbolAddress((void**)&W3l, g_W3l);
    cudaGetSymbolAddress((void**)&W4h, g_W4h);  cudaGetSymbolAddress((void**)&W4l, g_W4l);
    cudaGetSymbolAddress((void**)&b2f, g_b2f);
    cudaGetSymbolAddress((void**)&b4f, g_b4f);
    cudaGetSymbolAddress((void**)&st,  g_stats);
    cudaGetSymbolAddress((void**)&part,g_part);
    cudaGetSymbolAddress((void**)&nc,  g_nc);

    const int SMEM_A = A_HDR + A_ST * A_STAGE_B;   // 212992
    const int SMEM_B = B_HDR + B_ST * B_STAGE_B;   // 208896
    cudaFuncSetAttribute((const void*)gemm_a<0, false, 1>,
                         cudaFuncAttributeMaxDynamicSharedMemorySize, SMEM_A);
    cudaFuncSetAttribute((const void*)gemm_a<1, true, 1>,
                         cudaFuncAttributeMaxDynamicSharedMemorySize, SMEM_A);
    cudaFuncSetAttribute((const void*)gemm_b<1>,
                         cudaFuncAttributeMaxDynamicSharedMemorySize, SMEM_B);

    // 0) fused prep (x -> fp16, W1/W3 fp16 hi/lo splits, FIR noise)
    prep_kernel<<<SPLITX_BLOCKS + W1_BLOCKS + W3_BLOCKS + 1, 256>>>(
        x, x16, W1, W1h, W1l, W3, W3h, W3l, nz, fir, nc,
        out + (size_t)B_ROWS * BLK);

    // 1) h1 = prelu(x @ W1^T + b1) -> fp16, fused BN1 partials. Single-term W1.
    gemm_a<1, true, 1><<<dim3(BLK / 128, B_ROWS / 256), 512, SMEM_A>>>(
        x16, W1h, W1l, b1, nullptr, h1, B_ROWS, BLK, BLK, a1, part);

    // 2) BN1 reduce + fold into W2 (fp16 hi/lo)
    stats_reduce2<<<BLK, 256>>>(part, st, st + BLK, BLK);
    fold_kernel<<<CUN, 128>>>(W2, b2, gm1, bt1, st, st + BLK, W2h, W2l, b2f, BLK);

    // 3) yc = 16*(h1_bn @ W2^T + b2)/||row|| + noise -> fp16. Single-term W2.
    gemm_b<1><<<dim3(1, B_ROWS / 128), 256, SMEM_B>>>(
        h1, W2h, W2l, b2f, yc, B_ROWS, CUN, BLK, nc);

    // 4) d = prelu(yc @ W3^T + b3) -> fp16, fused BN2 partials. Single-term W3.
    gemm_a<1, true, 1><<<dim3(BLK / 128, B_ROWS / 256), 512, SMEM_A>>>(
        yc, W3h, W3l, b3, nullptr, dd, B_ROWS, BLK, CUN, a2, part);

    // 5) BN2 reduce + fold into W4
    stats_reduce2<<<BLK, 256>>>(part, st + 2 * BLK, st + 3 * BLK, BLK);
    fold_kernel<<<BLK, 128>>>(W4, b4, gm2, bt2, st + 2 * BLK, st + 3 * BLK, W4h, W4l, b4f, BLK);

    // 6) out = d_bn @ W4^T + b4 (fp32). Single-term W4.
    gemm_a<0, false, 1><<<dim3(BLK / 128, B_ROWS / 256), 512, SMEM_A>>>(
        dd, W4h, W4l, b4f, out, nullptr, B_ROWS, BLK, BLK, nullptr, nullptr);

    (void)in_sizes; (void)n_in; (void)out_size;
}